// round 4
// baseline (speedup 1.0000x reference)
#include <cuda_runtime.h>
#include <math.h>
#include <stdint.h>

#define B_SZ 2
#define T_SZ 2048
#define C_SZ 1024
#define NH   16
#define HD   64
#define M_SZ (B_SZ*T_SZ)   // 4096

// Scratch (static device globals: allowed; runtime allocation is not)
__device__ float g_q [B_SZ*NH*T_SZ*HD];   // [b][h][t][d]
__device__ float g_kt[B_SZ*NH*HD*T_SZ];   // [b][h][d][t]  (K stored d-major)
__device__ float g_v [B_SZ*NH*T_SZ*HD];   // [b][h][t][d]
__device__ float g_y [M_SZ*C_SZ];         // [b*t][c]

__device__ __forceinline__ uint32_t f2tf(float f){
    uint32_t u; asm("cvt.rna.tf32.f32 %0, %1;" : "=r"(u) : "f"(f)); return u;
}

// m16n8k8 tf32 mma, D += A*B (C aliased to D)
__device__ __forceinline__ void mma8(float* d, const uint32_t* a, const uint32_t* b){
    asm volatile("mma.sync.aligned.m16n8k8.row.col.f32.tf32.tf32.f32 "
        "{%0,%1,%2,%3}, {%4,%5,%6,%7}, {%8,%9}, {%0,%1,%2,%3};"
        : "+f"(d[0]), "+f"(d[1]), "+f"(d[2]), "+f"(d[3])
        : "r"(a[0]), "r"(a[1]), "r"(a[2]), "r"(a[3]), "r"(b[0]), "r"(b[1]));
}

#define MODE_PLAIN   0
#define MODE_HEADS   1
#define MODE_HEADS_T 2

// ---------------------------------------------------------------------------
// tf32 GEMM core: 128x128 block tile, KC=32, 8 warps, warp 32x64.
// 2-stage smem double buffer, one barrier per K-iter, LDG prefetch to regs.
// ---------------------------------------------------------------------------
#define KC   32
#define ASTR 36    // [m 128][k 32 +4]  bank = (4m + k) & 31
#define BSTR 136   // [k 32][n 128 +8]  bank = (8k + n) & 31
#define GEMM_SMEM ((2*128*ASTR + 2*KC*BSTR) * 4)

__device__ __forceinline__ void gemm_core(
    const float* __restrict__ A, const float* __restrict__ W,
    const float* __restrict__ bias, float* __restrict__ out,
    uint32_t* __restrict__ sm, int bm, int bn, int mode)
{
    uint32_t* As[2] = { sm,                sm + 128*ASTR };
    uint32_t* Bs[2] = { sm + 2*128*ASTR,   sm + 2*128*ASTR + KC*BSTR };

    const int tid  = threadIdx.x;
    const int warp = tid >> 5, lane = tid & 31;
    const int gid  = lane >> 2, tig = lane & 3;
    const int warpM = (warp & 3) * 32, warpN = (warp >> 2) * 64;

    const int arow = tid >> 3, acol = (tid & 7) * 4;   // A: 32 rows/pass x 32 k
    const int brow = tid >> 5, bcol = (tid & 31) * 4;  // B: 8 k/pass x 128 n

    const float* Abase = A + (size_t)(bm + arow) * C_SZ + acol;
    const float* Wbase = W + (size_t)brow * C_SZ + bn + bcol;

    float4 pa[4], pb[4];
    #pragma unroll
    for (int p = 0; p < 4; p++){
        pa[p] = *(const float4*)(Abase + (size_t)(32*p) * C_SZ);
        pb[p] = *(const float4*)(Wbase + (size_t)(8*p) * C_SZ);
    }
    {   // stage 0 fill
        #pragma unroll
        for (int p = 0; p < 4; p++){
            *(uint4*)&As[0][(arow + 32*p)*ASTR + acol] =
                make_uint4(f2tf(pa[p].x), f2tf(pa[p].y), f2tf(pa[p].z), f2tf(pa[p].w));
            *(uint4*)&Bs[0][(brow + 8*p)*BSTR + bcol] =
                make_uint4(f2tf(pb[p].x), f2tf(pb[p].y), f2tf(pb[p].z), f2tf(pb[p].w));
        }
    }
    __syncthreads();

    float acc[2][8][4];
    #pragma unroll
    for (int mt = 0; mt < 2; mt++)
        #pragma unroll
        for (int nt = 0; nt < 8; nt++)
            #pragma unroll
            for (int e = 0; e < 4; e++) acc[mt][nt][e] = 0.f;

    int stage = 0;
    for (int k0 = 0; k0 < C_SZ; k0 += KC){
        const bool more = (k0 + KC < C_SZ);
        if (more){
            #pragma unroll
            for (int p = 0; p < 4; p++){
                pa[p] = *(const float4*)(Abase + (k0 + KC) + (size_t)(32*p) * C_SZ);
                pb[p] = *(const float4*)(Wbase + (size_t)(k0 + KC + 8*p) * C_SZ);
            }
        }
        const uint32_t* Ac = As[stage];
        const uint32_t* Bc = Bs[stage];
        #pragma unroll
        for (int ks = 0; ks < KC; ks += 8){
            uint32_t af[2][4];
            #pragma unroll
            for (int mt = 0; mt < 2; mt++){
                const int r = warpM + mt*16 + gid;
                af[mt][0] = Ac[r*ASTR + ks + tig];
                af[mt][1] = Ac[(r+8)*ASTR + ks + tig];
                af[mt][2] = Ac[r*ASTR + ks + tig + 4];
                af[mt][3] = Ac[(r+8)*ASTR + ks + tig + 4];
            }
            #pragma unroll
            for (int nt = 0; nt < 8; nt++){
                const int c = warpN + nt*8 + gid;
                uint32_t bf[2] = { Bc[(ks+tig)*BSTR + c], Bc[(ks+tig+4)*BSTR + c] };
                mma8(acc[0][nt], af[0], bf);
                mma8(acc[1][nt], af[1], bf);
            }
        }
        if (more){
            const int ns = stage ^ 1;
            #pragma unroll
            for (int p = 0; p < 4; p++){
                *(uint4*)&As[ns][(arow + 32*p)*ASTR + acol] =
                    make_uint4(f2tf(pa[p].x), f2tf(pa[p].y), f2tf(pa[p].z), f2tf(pa[p].w));
                *(uint4*)&Bs[ns][(brow + 8*p)*BSTR + bcol] =
                    make_uint4(f2tf(pb[p].x), f2tf(pb[p].y), f2tf(pb[p].z), f2tf(pb[p].w));
            }
            __syncthreads();
            stage = ns;
        }
    }

    #pragma unroll
    for (int mt = 0; mt < 2; mt++){
        #pragma unroll
        for (int nt = 0; nt < 8; nt++){
            const int r = bm + warpM + mt*16 + gid;
            const int c = bn + warpN + nt*8 + 2*tig;
            const float b0v = bias[c], b1v = bias[c+1];
            float2 v0 = make_float2(acc[mt][nt][0] + b0v, acc[mt][nt][1] + b1v);
            float2 v1 = make_float2(acc[mt][nt][2] + b0v, acc[mt][nt][3] + b1v);
            if (mode == MODE_PLAIN){
                *(float2*)&out[(size_t)r * C_SZ + c]     = v0;
                *(float2*)&out[(size_t)(r+8) * C_SZ + c] = v1;
            } else {
                const int b = r >> 11, t = r & 2047;
                const int h = c >> 6,  d = c & 63;
                if (mode == MODE_HEADS){
                    *(float2*)&out[(((size_t)(b*NH + h)) * T_SZ + t    ) * HD + d] = v0;
                    *(float2*)&out[(((size_t)(b*NH + h)) * T_SZ + t + 8) * HD + d] = v1;
                } else {
                    const size_t base = ((size_t)(b*NH + h) * HD + d) * T_SZ + t;
                    out[base]            = v0.x;
                    out[base + T_SZ]     = v0.y;
                    out[base + 8]        = v1.x;
                    out[base + T_SZ + 8] = v1.y;
                }
            }
        }
    }
}

// Fused QKV: grid.x = 24 (8 n-blocks x 3 matrices), grid.y = 32 (m-blocks)
__global__ __launch_bounds__(256, 2)
void qkv_gemm(const float* __restrict__ x,
              const float* __restrict__ Wq, const float* __restrict__ bq,
              const float* __restrict__ Wk, const float* __restrict__ bk,
              const float* __restrict__ Wv, const float* __restrict__ bv,
              float* __restrict__ q, float* __restrict__ kt, float* __restrict__ v)
{
    extern __shared__ uint32_t gsm[];
    const int bx = blockIdx.x;
    const int which = bx >> 3;
    const int bn = (bx & 7) * 128;
    const int bm = blockIdx.y * 128;
    const float* W    = (which == 0) ? Wq : (which == 1) ? Wk : Wv;
    const float* bias = (which == 0) ? bq : (which == 1) ? bk : bv;
    float* out        = (which == 0) ? q  : (which == 1) ? kt : v;
    const int mode    = (which == 1) ? MODE_HEADS_T : MODE_HEADS;
    gemm_core(x, W, bias, out, gsm, bm, bn, mode);
}

__global__ __launch_bounds__(256, 2)
void oproj_gemm(const float* __restrict__ A, const float* __restrict__ W,
                const float* __restrict__ bias, float* __restrict__ out)
{
    extern __shared__ uint32_t gsm[];
    gemm_core(A, W, bias, out, gsm, blockIdx.y * 128, blockIdx.x * 128, MODE_PLAIN);
}

// ---------------------------------------------------------------------------
// Flash attention, tf32 mma. 128 thr (4 warps), BQ=64 (16 rows/warp), BK=64.
// Next-tile K/V prefetched into registers -> global latency hidden by compute.
// ---------------------------------------------------------------------------
#define SQ 68   // [row 64][64+4]: A-operand banks (4r + k) & 31 -> 32-distinct
#define SK 72   // [k 64][64+8]:   B-operand banks (8k + n) & 31 -> 32-distinct
#define FLASH_SMEM ((64*SQ + 64*SK + 64*SK + 64*SQ) * 4)

__global__ __launch_bounds__(128, 3)
void flash_tc(const float* __restrict__ Q, const float* __restrict__ Kt,
              const float* __restrict__ V, float* __restrict__ Y)
{
    extern __shared__ uint32_t smbuf[];
    uint32_t* Qs = smbuf;            // [q][d]   A-operand (pre-scaled tf32)
    uint32_t* Ks = Qs + 64*SQ;       // [d][key] B-operand
    uint32_t* Vs = Ks + 64*SK;       // [key][d] B-operand
    uint32_t* Ps = Vs + 64*SK;       // [q][key] A-operand

    const int tid  = threadIdx.x;
    const int warp = tid >> 5, lane = tid & 31;
    const int gid  = lane >> 2, tig = lane & 3;
    const int qt   = (int)gridDim.x - 1 - (int)blockIdx.x;  // heavy blocks first
    const int h    = blockIdx.y, b = blockIdx.z;
    const int bh   = b * NH + h;
    const int q0   = qt * 64;
    const int wrow = warp * 16;
    const float slope = exp2f(-0.5f * (float)(h + 1));

    const int lr = tid >> 4, lc = (tid & 15) * 4;  // loader coords

    const float* kb_base = Kt + (size_t)bh * HD * T_SZ;   // [d][t]
    const float* vb_base = V  + (size_t)bh * T_SZ * HD;   // [t][d]

    float4 kr[8], vr[8];
    #pragma unroll
    for (int p = 0; p < 8; p++){   // prefetch tile 0
        kr[p] = *(const float4*)(kb_base + (size_t)(lr + 8*p) * T_SZ + lc);
        vr[p] = *(const float4*)(vb_base + (size_t)(lr + 8*p) * HD + lc);
    }

    {   // Q tile, pre-scaled by 1/sqrt(hd)
        const float* qb = Q + ((size_t)bh * T_SZ + q0) * HD;
        #pragma unroll
        for (int p = 0; p < 8; p++){
            float4 v = *(const float4*)(qb + (size_t)(lr + 8*p) * HD + lc);
            *(uint4*)&Qs[(lr + 8*p)*SQ + lc] = make_uint4(
                f2tf(v.x*0.125f), f2tf(v.y*0.125f), f2tf(v.z*0.125f), f2tf(v.w*0.125f));
        }
    }

    float m0 = -1e30f, m1 = -1e30f, l0 = 0.f, l1 = 0.f;
    float acc[8][4] = {};

    const int nkt = qt + 1;
    for (int kt = 0; kt < nkt; kt++){
        const int k0 = kt * 64;
        __syncthreads();   // previous tile's matmuls done with Ks/Vs
        #pragma unroll
        for (int p = 0; p < 8; p++){
            *(uint4*)&Ks[(lr + 8*p)*SK + lc] =
                make_uint4(f2tf(kr[p].x), f2tf(kr[p].y), f2tf(kr[p].z), f2tf(kr[p].w));
            *(uint4*)&Vs[(lr + 8*p)*SK + lc] =
                make_uint4(f2tf(vr[p].x), f2tf(vr[p].y), f2tf(vr[p].z), f2tf(vr[p].w));
        }
        __syncthreads();   // publish K/V (and Qs on iter 0)

        if (kt + 1 < nkt){   // prefetch next tile; latency hidden by compute below
            const int kn = k0 + 64;
            #pragma unroll
            for (int p = 0; p < 8; p++){
                kr[p] = *(const float4*)(kb_base + kn + (size_t)(lr + 8*p) * T_SZ + lc);
                vr[p] = *(const float4*)(vb_base + (size_t)(kn + lr + 8*p) * HD + lc);
            }
        }

        // S = Q K^T : warp computes its 16 rows x 64 keys
        float s[8][4] = {};
        #pragma unroll
        for (int ks = 0; ks < 64; ks += 8){
            uint32_t af[4];
            af[0] = Qs[(wrow+gid  )*SQ + ks + tig];
            af[1] = Qs[(wrow+gid+8)*SQ + ks + tig];
            af[2] = Qs[(wrow+gid  )*SQ + ks + tig + 4];
            af[3] = Qs[(wrow+gid+8)*SQ + ks + tig + 4];
            #pragma unroll
            for (int nt = 0; nt < 8; nt++){
                uint32_t bf[2] = { Ks[(ks+tig)*SK + nt*8 + gid],
                                   Ks[(ks+tig+4)*SK + nt*8 + gid] };
                mma8(s[nt], af, bf);
            }
        }

        // ALiBi + causal mask + online softmax (fragment form)
        const bool diag = (kt == nkt - 1);
        const int qi0 = q0 + wrow + gid, qi1 = qi0 + 8;
        float mx0 = -1e30f, mx1 = -1e30f;
        #pragma unroll
        for (int nt = 0; nt < 8; nt++){
            #pragma unroll
            for (int e = 0; e < 2; e++){
                const int ki = k0 + nt*8 + 2*tig + e;
                float sv0 = s[nt][e]   - slope * (float)(qi0 - ki);
                float sv1 = s[nt][2+e] - slope * (float)(qi1 - ki);
                if (diag && ki > qi0) sv0 = -1e30f;
                if (diag && ki > qi1) sv1 = -1e30f;
                s[nt][e] = sv0; s[nt][2+e] = sv1;
                mx0 = fmaxf(mx0, sv0); mx1 = fmaxf(mx1, sv1);
            }
        }
        mx0 = fmaxf(mx0, __shfl_xor_sync(0xffffffffu, mx0, 1));
        mx0 = fmaxf(mx0, __shfl_xor_sync(0xffffffffu, mx0, 2));
        mx1 = fmaxf(mx1, __shfl_xor_sync(0xffffffffu, mx1, 1));
        mx1 = fmaxf(mx1, __shfl_xor_sync(0xffffffffu, mx1, 2));
        const float mn0 = fmaxf(m0, mx0), mn1 = fmaxf(m1, mx1);
        const float corr0 = __expf(m0 - mn0), corr1 = __expf(m1 - mn1);
        m0 = mn0; m1 = mn1;

        float ps0 = 0.f, ps1 = 0.f;
        #pragma unroll
        for (int nt = 0; nt < 8; nt++){
            const float p00 = __expf(s[nt][0] - mn0), p01 = __expf(s[nt][1] - mn0);
            const float p10 = __expf(s[nt][2] - mn1), p11 = __expf(s[nt][3] - mn1);
            ps0 += p00 + p01; ps1 += p10 + p11;
            const int cw = nt*8 + 2*tig;
            *(uint2*)&Ps[(wrow+gid  )*SQ + cw] = make_uint2(f2tf(p00), f2tf(p01));
            *(uint2*)&Ps[(wrow+gid+8)*SQ + cw] = make_uint2(f2tf(p10), f2tf(p11));
        }
        ps0 += __shfl_xor_sync(0xffffffffu, ps0, 1);
        ps0 += __shfl_xor_sync(0xffffffffu, ps0, 2);
        ps1 += __shfl_xor_sync(0xffffffffu, ps1, 1);
        ps1 += __shfl_xor_sync(0xffffffffu, ps1, 2);
        l0 = l0 * corr0 + ps0;
        l1 = l1 * corr1 + ps1;
        #pragma unroll
        for (int nt = 0; nt < 8; nt++){
            acc[nt][0] *= corr0; acc[nt][1] *= corr0;
            acc[nt][2] *= corr1; acc[nt][3] *= corr1;
        }
        __syncwarp();   // Ps rows are warp-private; publish stores to lanes

        // acc += P @ V
        #pragma unroll
        for (int ks = 0; ks < 64; ks += 8){
            uint32_t af[4];
            af[0] = Ps[(wrow+gid  )*SQ + ks + tig];
            af[1] = Ps[(wrow+gid+8)*SQ + ks + tig];
            af[2] = Ps[(wrow+gid  )*SQ + ks + tig + 4];
            af[3] = Ps[(wrow+gid+8)*SQ + ks + tig + 4];
            #pragma unroll
            for (int nt = 0; nt < 8; nt++){
                uint32_t bf[2] = { Vs[(ks+tig)*SK + nt*8 + gid],
                                   Vs[(ks+tig+4)*SK + nt*8 + gid] };
                mma8(acc[nt], af, bf);
            }
        }
        __syncwarp();
    }

    const float i0 = 1.f / l0, i1 = 1.f / l1;
    float* yb = Y + ((size_t)(b*T_SZ) + q0 + wrow) * C_SZ + h*HD;
    #pragma unroll
    for (int nt = 0; nt < 8; nt++){
        const int c = nt*8 + 2*tig;
        *(float2*)&yb[(size_t)gid     * C_SZ + c] = make_float2(acc[nt][0]*i0, acc[nt][1]*i0);
        *(float2*)&yb[(size_t)(gid+8) * C_SZ + c] = make_float2(acc[nt][2]*i1, acc[nt][3]*i1);
    }
}

extern "C" void kernel_launch(void* const* d_in, const int* in_sizes, int n_in,
                              void* d_out, int out_size)
{
    const float* x  = (const float*)d_in[0];
    const float* Wq = (const float*)d_in[1];
    const float* bq = (const float*)d_in[2];
    const float* Wk = (const float*)d_in[3];
    const float* bk = (const float*)d_in[4];
    const float* Wv = (const float*)d_in[5];
    const float* bv = (const float*)d_in[6];
    const float* Wo = (const float*)d_in[7];
    const float* bo = (const float*)d_in[8];
    float* out = (float*)d_out;

    float *qp, *ktp, *vp, *yp;
    cudaGetSymbolAddress((void**)&qp,  g_q);
    cudaGetSymbolAddress((void**)&ktp, g_kt);
    cudaGetSymbolAddress((void**)&vp,  g_v);
    cudaGetSymbolAddress((void**)&yp,  g_y);

    cudaFuncSetAttribute(qkv_gemm,
                         cudaFuncAttributeMaxDynamicSharedMemorySize, GEMM_SMEM);
    cudaFuncSetAttribute(oproj_gemm,
                         cudaFuncAttributeMaxDynamicSharedMemorySize, GEMM_SMEM);
    cudaFuncSetAttribute(flash_tc,
                         cudaFuncAttributeMaxDynamicSharedMemorySize, FLASH_SMEM);

    qkv_gemm<<<dim3(24, M_SZ/128), 256, GEMM_SMEM>>>(x, Wq, bq, Wk, bk, Wv, bv,
                                                     qp, ktp, vp);

    flash_tc<<<dim3(T_SZ/64, NH, B_SZ), 128, FLASH_SMEM>>>(qp, ktp, vp, yp);

    oproj_gemm<<<dim3(C_SZ/128, M_SZ/128), 256, GEMM_SMEM>>>(yp, Wo, bo, out);
}

// round 5
// speedup vs baseline: 1.0552x; 1.0552x over previous
#include <cuda_runtime.h>
#include <math.h>
#include <stdint.h>

#define B_SZ 2
#define T_SZ 2048
#define C_SZ 1024
#define NH   16
#define HD   64
#define M_SZ (B_SZ*T_SZ)   // 4096

// Scratch (static device globals: allowed; runtime allocation is not)
__device__ float g_q [B_SZ*NH*T_SZ*HD];   // [b][h][t][d]
__device__ float g_kt[B_SZ*NH*HD*T_SZ];   // [b][h][d][t]  (K stored d-major)
__device__ float g_v [B_SZ*NH*T_SZ*HD];   // [b][h][t][d]
__device__ float g_y [M_SZ*C_SZ];         // [b*t][c]

__device__ __forceinline__ uint32_t f2tf(float f){
    uint32_t u; asm("cvt.rna.tf32.f32 %0, %1;" : "=r"(u) : "f"(f)); return u;
}

// m16n8k8 tf32 mma, D += A*B (C aliased to D)
__device__ __forceinline__ void mma8(float* d, const uint32_t* a, const uint32_t* b){
    asm volatile("mma.sync.aligned.m16n8k8.row.col.f32.tf32.tf32.f32 "
        "{%0,%1,%2,%3}, {%4,%5,%6,%7}, {%8,%9}, {%0,%1,%2,%3};"
        : "+f"(d[0]), "+f"(d[1]), "+f"(d[2]), "+f"(d[3])
        : "r"(a[0]), "r"(a[1]), "r"(a[2]), "r"(a[3]), "r"(b[0]), "r"(b[1]));
}

#define MODE_PLAIN   0
#define MODE_HEADS   1
#define MODE_HEADS_T 2

// ---------------------------------------------------------------------------
// tf32 GEMM core (R2 single-buffer version): 128x128 tile, KC=32, 8 warps,
// warp tile 32x64. LDG next tile into regs between the two barriers.
// ---------------------------------------------------------------------------
#define KC   32
#define ASTR 36    // [m 128][k 32 +4]  bank = (4m + k) & 31
#define BSTR 136   // [k 32][n 128 +8]  bank = (8k + n) & 31

__device__ __forceinline__ void gemm_core(
    const float* __restrict__ A, const float* __restrict__ W,
    const float* __restrict__ bias, float* __restrict__ out,
    int bm, int bn, int mode)
{
    __shared__ uint32_t As[128*ASTR];
    __shared__ uint32_t Bs[KC*BSTR];

    const int tid  = threadIdx.x;
    const int warp = tid >> 5, lane = tid & 31;
    const int gid  = lane >> 2, tig = lane & 3;
    const int warpM = (warp & 3) * 32, warpN = (warp >> 2) * 64;

    const int arow = tid >> 3, acol = (tid & 7) * 4;   // A: 32 rows/pass x 32 k
    const int brow = tid >> 5, bcol = (tid & 31) * 4;  // B: 8 k/pass x 128 n

    const float* Abase = A + (size_t)(bm + arow) * C_SZ + acol;
    const float* Wbase = W + (size_t)brow * C_SZ + bn + bcol;

    float4 pa[4], pb[4];
    #pragma unroll
    for (int p = 0; p < 4; p++){
        pa[p] = *(const float4*)(Abase + (size_t)(32*p) * C_SZ);
        pb[p] = *(const float4*)(Wbase + (size_t)(8*p) * C_SZ);
    }

    float acc[2][8][4];
    #pragma unroll
    for (int mt = 0; mt < 2; mt++)
        #pragma unroll
        for (int nt = 0; nt < 8; nt++)
            #pragma unroll
            for (int e = 0; e < 4; e++) acc[mt][nt][e] = 0.f;

    for (int k0 = 0; k0 < C_SZ; k0 += KC){
        #pragma unroll
        for (int p = 0; p < 4; p++){
            *(uint4*)&As[(arow + 32*p)*ASTR + acol] =
                make_uint4(f2tf(pa[p].x), f2tf(pa[p].y), f2tf(pa[p].z), f2tf(pa[p].w));
            *(uint4*)&Bs[(brow + 8*p)*BSTR + bcol] =
                make_uint4(f2tf(pb[p].x), f2tf(pb[p].y), f2tf(pb[p].z), f2tf(pb[p].w));
        }
        __syncthreads();

        if (k0 + KC < C_SZ){
            #pragma unroll
            for (int p = 0; p < 4; p++){
                pa[p] = *(const float4*)(Abase + (k0 + KC) + (size_t)(32*p) * C_SZ);
                pb[p] = *(const float4*)(Wbase + (size_t)(k0 + KC + 8*p) * C_SZ);
            }
        }

        #pragma unroll
        for (int ks = 0; ks < KC; ks += 8){
            uint32_t af[2][4];
            #pragma unroll
            for (int mt = 0; mt < 2; mt++){
                const int r = warpM + mt*16 + gid;
                af[mt][0] = As[r*ASTR + ks + tig];
                af[mt][1] = As[(r+8)*ASTR + ks + tig];
                af[mt][2] = As[r*ASTR + ks + tig + 4];
                af[mt][3] = As[(r+8)*ASTR + ks + tig + 4];
            }
            #pragma unroll
            for (int nt = 0; nt < 8; nt++){
                const int c = warpN + nt*8 + gid;
                uint32_t bf[2] = { Bs[(ks+tig)*BSTR + c], Bs[(ks+tig+4)*BSTR + c] };
                mma8(acc[0][nt], af[0], bf);
                mma8(acc[1][nt], af[1], bf);
            }
        }
        __syncthreads();
    }

    #pragma unroll
    for (int mt = 0; mt < 2; mt++){
        #pragma unroll
        for (int nt = 0; nt < 8; nt++){
            const int r = bm + warpM + mt*16 + gid;
            const int c = bn + warpN + nt*8 + 2*tig;
            const float b0v = bias[c], b1v = bias[c+1];
            float2 v0 = make_float2(acc[mt][nt][0] + b0v, acc[mt][nt][1] + b1v);
            float2 v1 = make_float2(acc[mt][nt][2] + b0v, acc[mt][nt][3] + b1v);
            if (mode == MODE_PLAIN){
                *(float2*)&out[(size_t)r * C_SZ + c]     = v0;
                *(float2*)&out[(size_t)(r+8) * C_SZ + c] = v1;
            } else {
                const int b = r >> 11, t = r & 2047;
                const int h = c >> 6,  d = c & 63;
                if (mode == MODE_HEADS){
                    *(float2*)&out[(((size_t)(b*NH + h)) * T_SZ + t    ) * HD + d] = v0;
                    *(float2*)&out[(((size_t)(b*NH + h)) * T_SZ + t + 8) * HD + d] = v1;
                } else {
                    const size_t base = ((size_t)(b*NH + h) * HD + d) * T_SZ + t;
                    out[base]            = v0.x;
                    out[base + T_SZ]     = v0.y;
                    out[base + 8]        = v1.x;
                    out[base + T_SZ + 8] = v1.y;
                }
            }
        }
    }
}

// Fused QKV: grid.x = 24 (8 n-blocks x 3 matrices), grid.y = 32 (m-blocks)
__global__ __launch_bounds__(256, 2)
void qkv_gemm(const float* __restrict__ x,
              const float* __restrict__ Wq, const float* __restrict__ bq,
              const float* __restrict__ Wk, const float* __restrict__ bk,
              const float* __restrict__ Wv, const float* __restrict__ bv,
              float* __restrict__ q, float* __restrict__ kt, float* __restrict__ v)
{
    const int bx = blockIdx.x;
    const int which = bx >> 3;
    const int bn = (bx & 7) * 128;
    const int bm = blockIdx.y * 128;
    const float* W    = (which == 0) ? Wq : (which == 1) ? Wk : Wv;
    const float* bias = (which == 0) ? bq : (which == 1) ? bk : bv;
    float* out        = (which == 0) ? q  : (which == 1) ? kt : v;
    const int mode    = (which == 1) ? MODE_HEADS_T : MODE_HEADS;
    gemm_core(x, W, bias, out, bm, bn, mode);
}

__global__ __launch_bounds__(256, 2)
void oproj_gemm(const float* __restrict__ A, const float* __restrict__ W,
                const float* __restrict__ bias, float* __restrict__ out)
{
    gemm_core(A, W, bias, out, blockIdx.y * 128, blockIdx.x * 128, MODE_PLAIN);
}

// ---------------------------------------------------------------------------
// Flash attention, tf32 mma. 256 thr (8 warps), BQ=128 (16 rows/warp), BK=64.
// K/V tile feeds 128 q-rows: half the smem-fill + sync per unit work vs BQ=64.
// ---------------------------------------------------------------------------
#define SQ 68   // [row][64+4]: A-operand banks (4r + k) & 31 -> 32-distinct
#define SK 72   // [k][64+8]:   B-operand banks (8k + n) & 31 -> 32-distinct
#define FLASH_SMEM ((128*SQ + 64*SK + 64*SK + 128*SQ) * 4)

__global__ __launch_bounds__(256, 2)
void flash_tc(const float* __restrict__ Q, const float* __restrict__ Kt,
              const float* __restrict__ V, float* __restrict__ Y)
{
    extern __shared__ uint32_t smbuf[];
    uint32_t* Qs = smbuf;            // [128][SQ]  A-operand (pre-scaled tf32)
    uint32_t* Ks = Qs + 128*SQ;      // [64 d][64 k] B-operand
    uint32_t* Vs = Ks + 64*SK;       // [64 k][64 d] B-operand
    uint32_t* Ps = Vs + 64*SK;       // [128][SQ]  A-operand

    const int tid  = threadIdx.x;
    const int warp = tid >> 5, lane = tid & 31;
    const int gid  = lane >> 2, tig = lane & 3;
    const int qt   = (int)gridDim.x - 1 - (int)blockIdx.x;  // heavy blocks first
    const int h    = blockIdx.y, b = blockIdx.z;
    const int bh   = b * NH + h;
    const int q0   = qt * 128;
    const int wrow = warp * 16;
    const float slope = exp2f(-0.5f * (float)(h + 1));

    const int lr = tid >> 4, lc = (tid & 15) * 4;  // loader coords (16 rows/pass)

    const float* kb_base = Kt + (size_t)bh * HD * T_SZ;   // [d][t]
    const float* vb_base = V  + (size_t)bh * T_SZ * HD;   // [t][d]

    {   // Q tile (128 rows), pre-scaled by 1/sqrt(hd)
        const float* qb = Q + ((size_t)bh * T_SZ + q0) * HD;
        #pragma unroll
        for (int p = 0; p < 8; p++){
            const int row = lr + 16*p;
            float4 v = *(const float4*)(qb + (size_t)row * HD + lc);
            *(uint4*)&Qs[row*SQ + lc] = make_uint4(
                f2tf(v.x*0.125f), f2tf(v.y*0.125f), f2tf(v.z*0.125f), f2tf(v.w*0.125f));
        }
    }

    float m0 = -1e30f, m1 = -1e30f, l0 = 0.f, l1 = 0.f;
    float acc[8][4] = {};

    const int nkt = 2*qt + 2;
    for (int kt = 0; kt < nkt; kt++){
        const int k0 = kt * 64;
        __syncthreads();   // previous tile's matmuls done with Ks/Vs
        #pragma unroll
        for (int p = 0; p < 4; p++){
            const int row = lr + 16*p;   // d for K, key for V
            float4 kv = *(const float4*)(kb_base + (size_t)row * T_SZ + k0 + lc);
            *(uint4*)&Ks[row*SK + lc] =
                make_uint4(f2tf(kv.x), f2tf(kv.y), f2tf(kv.z), f2tf(kv.w));
            float4 vv = *(const float4*)(vb_base + (size_t)(k0 + row) * HD + lc);
            *(uint4*)&Vs[row*SK + lc] =
                make_uint4(f2tf(vv.x), f2tf(vv.y), f2tf(vv.z), f2tf(vv.w));
        }
        __syncthreads();   // publish K/V (and Qs on iter 0)

        // S = Q K^T : warp computes its 16 rows x 64 keys
        float s[8][4] = {};
        #pragma unroll
        for (int ks = 0; ks < 64; ks += 8){
            uint32_t af[4];
            af[0] = Qs[(wrow+gid  )*SQ + ks + tig];
            af[1] = Qs[(wrow+gid+8)*SQ + ks + tig];
            af[2] = Qs[(wrow+gid  )*SQ + ks + tig + 4];
            af[3] = Qs[(wrow+gid+8)*SQ + ks + tig + 4];
            #pragma unroll
            for (int nt = 0; nt < 8; nt++){
                uint32_t bf[2] = { Ks[(ks+tig)*SK + nt*8 + gid],
                                   Ks[(ks+tig+4)*SK + nt*8 + gid] };
                mma8(s[nt], af, bf);
            }
        }

        // ALiBi + causal mask + online softmax (fragment form)
        const bool diag = (k0 + 63 > q0 + wrow);   // this warp's rows may mask
        const int qi0 = q0 + wrow + gid, qi1 = qi0 + 8;
        float mx0 = -1e30f, mx1 = -1e30f;
        #pragma unroll
        for (int nt = 0; nt < 8; nt++){
            #pragma unroll
            for (int e = 0; e < 2; e++){
                const int ki = k0 + nt*8 + 2*tig + e;
                float sv0 = s[nt][e]   - slope * (float)(qi0 - ki);
                float sv1 = s[nt][2+e] - slope * (float)(qi1 - ki);
                if (diag && ki > qi0) sv0 = -1e30f;
                if (diag && ki > qi1) sv1 = -1e30f;
                s[nt][e] = sv0; s[nt][2+e] = sv1;
                mx0 = fmaxf(mx0, sv0); mx1 = fmaxf(mx1, sv1);
            }
        }
        mx0 = fmaxf(mx0, __shfl_xor_sync(0xffffffffu, mx0, 1));
        mx0 = fmaxf(mx0, __shfl_xor_sync(0xffffffffu, mx0, 2));
        mx1 = fmaxf(mx1, __shfl_xor_sync(0xffffffffu, mx1, 1));
        mx1 = fmaxf(mx1, __shfl_xor_sync(0xffffffffu, mx1, 2));
        const float mn0 = fmaxf(m0, mx0), mn1 = fmaxf(m1, mx1);
        const float corr0 = __expf(m0 - mn0), corr1 = __expf(m1 - mn1);
        m0 = mn0; m1 = mn1;

        float ps0 = 0.f, ps1 = 0.f;
        #pragma unroll
        for (int nt = 0; nt < 8; nt++){
            const float p00 = __expf(s[nt][0] - mn0), p01 = __expf(s[nt][1] - mn0);
            const float p10 = __expf(s[nt][2] - mn1), p11 = __expf(s[nt][3] - mn1);
            ps0 += p00 + p01; ps1 += p10 + p11;
            const int cw = nt*8 + 2*tig;
            *(uint2*)&Ps[(wrow+gid  )*SQ + cw] = make_uint2(f2tf(p00), f2tf(p01));
            *(uint2*)&Ps[(wrow+gid+8)*SQ + cw] = make_uint2(f2tf(p10), f2tf(p11));
        }
        ps0 += __shfl_xor_sync(0xffffffffu, ps0, 1);
        ps0 += __shfl_xor_sync(0xffffffffu, ps0, 2);
        ps1 += __shfl_xor_sync(0xffffffffu, ps1, 1);
        ps1 += __shfl_xor_sync(0xffffffffu, ps1, 2);
        l0 = l0 * corr0 + ps0;
        l1 = l1 * corr1 + ps1;
        #pragma unroll
        for (int nt = 0; nt < 8; nt++){
            acc[nt][0] *= corr0; acc[nt][1] *= corr0;
            acc[nt][2] *= corr1; acc[nt][3] *= corr1;
        }
        __syncwarp();   // Ps rows are warp-private; publish stores to lanes

        // acc += P @ V
        #pragma unroll
        for (int ks = 0; ks < 64; ks += 8){
            uint32_t af[4];
            af[0] = Ps[(wrow+gid  )*SQ + ks + tig];
            af[1] = Ps[(wrow+gid+8)*SQ + ks + tig];
            af[2] = Ps[(wrow+gid  )*SQ + ks + tig + 4];
            af[3] = Ps[(wrow+gid+8)*SQ + ks + tig + 4];
            #pragma unroll
            for (int nt = 0; nt < 8; nt++){
                uint32_t bf[2] = { Vs[(ks+tig)*SK + nt*8 + gid],
                                   Vs[(ks+tig+4)*SK + nt*8 + gid] };
                mma8(acc[nt], af, bf);
            }
        }
        __syncwarp();
    }

    const float i0 = 1.f / l0, i1 = 1.f / l1;
    float* yb = Y + ((size_t)(b*T_SZ) + q0 + wrow) * C_SZ + h*HD;
    #pragma unroll
    for (int nt = 0; nt < 8; nt++){
        const int c = nt*8 + 2*tig;
        *(float2*)&yb[(size_t)gid     * C_SZ + c] = make_float2(acc[nt][0]*i0, acc[nt][1]*i0);
        *(float2*)&yb[(size_t)(gid+8) * C_SZ + c] = make_float2(acc[nt][2]*i1, acc[nt][3]*i1);
    }
}

extern "C" void kernel_launch(void* const* d_in, const int* in_sizes, int n_in,
                              void* d_out, int out_size)
{
    const float* x  = (const float*)d_in[0];
    const float* Wq = (const float*)d_in[1];
    const float* bq = (const float*)d_in[2];
    const float* Wk = (const float*)d_in[3];
    const float* bk = (const float*)d_in[4];
    const float* Wv = (const float*)d_in[5];
    const float* bv = (const float*)d_in[6];
    const float* Wo = (const float*)d_in[7];
    const float* bo = (const float*)d_in[8];
    float* out = (float*)d_out;

    float *qp, *ktp, *vp, *yp;
    cudaGetSymbolAddress((void**)&qp,  g_q);
    cudaGetSymbolAddress((void**)&ktp, g_kt);
    cudaGetSymbolAddress((void**)&vp,  g_v);
    cudaGetSymbolAddress((void**)&yp,  g_y);

    cudaFuncSetAttribute(flash_tc,
                         cudaFuncAttributeMaxDynamicSharedMemorySize, FLASH_SMEM);

    qkv_gemm<<<dim3(24, M_SZ/128), 256>>>(x, Wq, bq, Wk, bk, Wv, bv, qp, ktp, vp);

    flash_tc<<<dim3(T_SZ/128, NH, B_SZ), 256, FLASH_SMEM>>>(qp, ktp, vp, yp);

    oproj_gemm<<<dim3(C_SZ/128, M_SZ/128), 256>>>(yp, Wo, bo, out);
}

// round 6
// speedup vs baseline: 1.6964x; 1.6077x over previous
#include <cuda_runtime.h>
#include <math.h>
#include <stdint.h>

#define B_SZ 2
#define T_SZ 2048
#define C_SZ 1024
#define NH   16
#define HD   64
#define M_SZ (B_SZ*T_SZ)   // 4096

// Scratch (static device globals: allowed; runtime allocation is not)
__device__ float g_q [B_SZ*NH*T_SZ*HD];   // [b][h][t][d]
__device__ float g_kt[B_SZ*NH*HD*T_SZ];   // [b][h][d][t]  (K stored d-major)
__device__ float g_v [B_SZ*NH*T_SZ*HD];   // [b][h][t][d]
__device__ float g_y [M_SZ*C_SZ];         // [b*t][c]

// pack two f32 -> f16x2 (lo, hi), round-to-nearest-even
__device__ __forceinline__ uint32_t pk(float lo, float hi){
    uint32_t r; asm("cvt.rn.f16x2.f32 %0, %1, %2;" : "=r"(r) : "f"(hi), "f"(lo));
    return r;
}

// m16n8k16 fp16 mma, fp32 accumulate, D += A*B (C aliased to D)
__device__ __forceinline__ void mma16(float* d, const uint32_t* a, const uint32_t* b){
    asm volatile("mma.sync.aligned.m16n8k16.row.col.f32.f16.f16.f32 "
        "{%0,%1,%2,%3}, {%4,%5,%6,%7}, {%8,%9}, {%0,%1,%2,%3};"
        : "+f"(d[0]), "+f"(d[1]), "+f"(d[2]), "+f"(d[3])
        : "r"(a[0]), "r"(a[1]), "r"(a[2]), "r"(a[3]), "r"(b[0]), "r"(b[1]));
}

#define MODE_PLAIN   0
#define MODE_HEADS   1
#define MODE_HEADS_T 2

// ---------------------------------------------------------------------------
// fp16 GEMM core: 128x128 tile, KC=32, 8 warps, warp tile 32x64.
// A smem: [m 128][k2 16 +4] half2 packed along k. Frag banks (4m+tig): 32-distinct.
// B smem: [k2 16][n 128 +8] half2 (k even, k odd) per n. Frag banks (8k2+n).
// ---------------------------------------------------------------------------
#define KC   32
#define AS   20
#define BS2  136

__device__ __forceinline__ void gemm_core(
    const float* __restrict__ A, const float* __restrict__ W,
    const float* __restrict__ bias, float* __restrict__ out,
    int bm, int bn, int mode)
{
    __shared__ uint32_t As[128*AS];
    __shared__ uint32_t Bs[16*BS2];

    const int tid  = threadIdx.x;
    const int warp = tid >> 5, lane = tid & 31;
    const int gid  = lane >> 2, tig = lane & 3;
    const int warpM = (warp & 3) * 32, warpN = (warp >> 2) * 64;

    const int arow = tid >> 3, acol = (tid & 7) * 4;   // A: 32 rows/pass, 4 passes
    const int k2r  = tid >> 5, bcol = (tid & 31) * 4;  // B: 8 k2-rows/pass, 2 passes

    const float* Abase = A + (size_t)(bm + arow) * C_SZ + acol;
    const float* Wb0   = W + (size_t)(2*k2r) * C_SZ + bn + bcol;

    float4 pa[4], pb0[2], pb1[2];
    #pragma unroll
    for (int p = 0; p < 4; p++)
        pa[p] = *(const float4*)(Abase + (size_t)(32*p) * C_SZ);
    #pragma unroll
    for (int p = 0; p < 2; p++){
        pb0[p] = *(const float4*)(Wb0 + (size_t)(16*p) * C_SZ);
        pb1[p] = *(const float4*)(Wb0 + (size_t)(16*p + 1) * C_SZ);
    }

    float acc[2][8][4];
    #pragma unroll
    for (int mt = 0; mt < 2; mt++)
        #pragma unroll
        for (int nt = 0; nt < 8; nt++)
            #pragma unroll
            for (int e = 0; e < 4; e++) acc[mt][nt][e] = 0.f;

    for (int k0 = 0; k0 < C_SZ; k0 += KC){
        #pragma unroll
        for (int p = 0; p < 4; p++)
            *(uint2*)&As[(arow + 32*p)*AS + (acol >> 1)] =
                make_uint2(pk(pa[p].x, pa[p].y), pk(pa[p].z, pa[p].w));
        #pragma unroll
        for (int p = 0; p < 2; p++)
            *(uint4*)&Bs[(k2r + 8*p)*BS2 + bcol] =
                make_uint4(pk(pb0[p].x, pb1[p].x), pk(pb0[p].y, pb1[p].y),
                           pk(pb0[p].z, pb1[p].z), pk(pb0[p].w, pb1[p].w));
        __syncthreads();

        if (k0 + KC < C_SZ){
            #pragma unroll
            for (int p = 0; p < 4; p++)
                pa[p] = *(const float4*)(Abase + (k0 + KC) + (size_t)(32*p) * C_SZ);
            #pragma unroll
            for (int p = 0; p < 2; p++){
                pb0[p] = *(const float4*)(Wb0 + (size_t)(k0 + KC + 16*p) * C_SZ);
                pb1[p] = *(const float4*)(Wb0 + (size_t)(k0 + KC + 16*p + 1) * C_SZ);
            }
        }

        #pragma unroll
        for (int ch = 0; ch < 2; ch++){      // two k16 chunks per KC=32
            const int kw = ch * 8;
            uint32_t af[2][4];
            #pragma unroll
            for (int mt = 0; mt < 2; mt++){
                const int r = warpM + mt*16 + gid;
                af[mt][0] = As[r*AS + kw + tig];
                af[mt][1] = As[(r+8)*AS + kw + tig];
                af[mt][2] = As[r*AS + kw + tig + 4];
                af[mt][3] = As[(r+8)*AS + kw + tig + 4];
            }
            #pragma unroll
            for (int nt = 0; nt < 8; nt++){
                const int c = warpN + nt*8 + gid;
                uint32_t bf[2] = { Bs[(kw+tig)*BS2 + c], Bs[(kw+tig+4)*BS2 + c] };
                mma16(acc[0][nt], af[0], bf);
                mma16(acc[1][nt], af[1], bf);
            }
        }
        __syncthreads();
    }

    #pragma unroll
    for (int mt = 0; mt < 2; mt++){
        #pragma unroll
        for (int nt = 0; nt < 8; nt++){
            const int r = bm + warpM + mt*16 + gid;
            const int c = bn + warpN + nt*8 + 2*tig;
            const float b0v = bias[c], b1v = bias[c+1];
            float2 v0 = make_float2(acc[mt][nt][0] + b0v, acc[mt][nt][1] + b1v);
            float2 v1 = make_float2(acc[mt][nt][2] + b0v, acc[mt][nt][3] + b1v);
            if (mode == MODE_PLAIN){
                *(float2*)&out[(size_t)r * C_SZ + c]     = v0;
                *(float2*)&out[(size_t)(r+8) * C_SZ + c] = v1;
            } else {
                const int b = r >> 11, t = r & 2047;
                const int h = c >> 6,  d = c & 63;
                if (mode == MODE_HEADS){
                    *(float2*)&out[(((size_t)(b*NH + h)) * T_SZ + t    ) * HD + d] = v0;
                    *(float2*)&out[(((size_t)(b*NH + h)) * T_SZ + t + 8) * HD + d] = v1;
                } else {
                    const size_t base = ((size_t)(b*NH + h) * HD + d) * T_SZ + t;
                    out[base]            = v0.x;
                    out[base + T_SZ]     = v0.y;
                    out[base + 8]        = v1.x;
                    out[base + T_SZ + 8] = v1.y;
                }
            }
        }
    }
}

// Fused QKV: grid.x = 24 (8 n-blocks x 3 matrices), grid.y = 32 (m-blocks)
__global__ __launch_bounds__(256, 2)
void qkv_gemm(const float* __restrict__ x,
              const float* __restrict__ Wq, const float* __restrict__ bq,
              const float* __restrict__ Wk, const float* __restrict__ bk,
              const float* __restrict__ Wv, const float* __restrict__ bv,
              float* __restrict__ q, float* __restrict__ kt, float* __restrict__ v)
{
    const int bx = blockIdx.x;
    const int which = bx >> 3;
    const int bn = (bx & 7) * 128;
    const int bm = blockIdx.y * 128;
    const float* W    = (which == 0) ? Wq : (which == 1) ? Wk : Wv;
    const float* bias = (which == 0) ? bq : (which == 1) ? bk : bv;
    float* out        = (which == 0) ? q  : (which == 1) ? kt : v;
    const int mode    = (which == 1) ? MODE_HEADS_T : MODE_HEADS;
    gemm_core(x, W, bias, out, bm, bn, mode);
}

__global__ __launch_bounds__(256, 2)
void oproj_gemm(const float* __restrict__ A, const float* __restrict__ W,
                const float* __restrict__ bias, float* __restrict__ out)
{
    gemm_core(A, W, bias, out, blockIdx.y * 128, blockIdx.x * 128, MODE_PLAIN);
}

// ---------------------------------------------------------------------------
// Flash attention, fp16 mma. 128 thr (4 warps), BQ=64 (16 rows/warp), BK=64.
// Qs/Ps: [row][32 words +4]; Ks/Vs: [k2 32][64 +8] packed along k.
// ---------------------------------------------------------------------------
#define SQW 36
#define SKW 72
#define FLASH_SMEM ((64*SQW + 32*SKW + 32*SKW + 64*SQW) * 4)

__global__ __launch_bounds__(128, 4)
void flash_tc(const float* __restrict__ Q, const float* __restrict__ Kt,
              const float* __restrict__ V, float* __restrict__ Y)
{
    extern __shared__ uint32_t smbuf[];
    uint32_t* Qs = smbuf;            // [64 q][SQW]   A-operand (pre-scaled)
    uint32_t* Ks = Qs + 64*SQW;      // [32 d2][SKW]  B-operand
    uint32_t* Vs = Ks + 32*SKW;      // [32 t2][SKW]  B-operand
    uint32_t* Ps = Vs + 32*SKW;      // [64 q][SQW]   A-operand

    const int tid  = threadIdx.x;
    const int warp = tid >> 5, lane = tid & 31;
    const int gid  = lane >> 2, tig = lane & 3;
    const int qt   = (int)gridDim.x - 1 - (int)blockIdx.x;  // heavy blocks first
    const int h    = blockIdx.y, b = blockIdx.z;
    const int bh   = b * NH + h;
    const int q0   = qt * 64;
    const int wrow = warp * 16;
    const float slope = exp2f(-0.5f * (float)(h + 1));

    const int lr = tid >> 4, lc = (tid & 15) * 4;  // loader coords

    const float* kb_base = Kt + (size_t)bh * HD * T_SZ;   // [d][t]
    const float* vb_base = V  + (size_t)bh * T_SZ * HD;   // [t][d]

    {   // Q tile (64 rows x 64 d), pre-scaled by 1/sqrt(hd)
        const float* qb = Q + ((size_t)bh * T_SZ + q0) * HD;
        #pragma unroll
        for (int p = 0; p < 8; p++){
            const int row = lr + 8*p;
            float4 v = *(const float4*)(qb + (size_t)row * HD + lc);
            *(uint2*)&Qs[row*SQW + (lc >> 1)] =
                make_uint2(pk(v.x*0.125f, v.y*0.125f), pk(v.z*0.125f, v.w*0.125f));
        }
    }

    float m0 = -1e30f, m1 = -1e30f, l0 = 0.f, l1 = 0.f;
    float acc[8][4] = {};

    const int nkt = qt + 1;
    for (int kt = 0; kt < nkt; kt++){
        const int k0 = kt * 64;
        __syncthreads();   // previous tile's matmuls done with Ks/Vs
        #pragma unroll
        for (int p = 0; p < 4; p++){
            const int r2 = lr + 8*p;   // d2 for K, t2 for V
            // K: pack (d=2*r2, d=2*r2+1) along keys
            float4 ka = *(const float4*)(kb_base + (size_t)(2*r2  ) * T_SZ + k0 + lc);
            float4 kb = *(const float4*)(kb_base + (size_t)(2*r2+1) * T_SZ + k0 + lc);
            *(uint4*)&Ks[r2*SKW + lc] = make_uint4(
                pk(ka.x, kb.x), pk(ka.y, kb.y), pk(ka.z, kb.z), pk(ka.w, kb.w));
            // V: pack (t=k0+2*r2, t=k0+2*r2+1) along d
            float4 va = *(const float4*)(vb_base + (size_t)(k0 + 2*r2    ) * HD + lc);
            float4 vc = *(const float4*)(vb_base + (size_t)(k0 + 2*r2 + 1) * HD + lc);
            *(uint4*)&Vs[r2*SKW + lc] = make_uint4(
                pk(va.x, vc.x), pk(va.y, vc.y), pk(va.z, vc.z), pk(va.w, vc.w));
        }
        __syncthreads();   // publish K/V (and Qs on iter 0)

        // S = Q K^T : warp computes its 16 rows x 64 keys (4 k16 chunks)
        float s[8][4] = {};
        #pragma unroll
        for (int ch = 0; ch < 4; ch++){
            const int kw = ch * 8;
            uint32_t af[4];
            af[0] = Qs[(wrow+gid  )*SQW + kw + tig];
            af[1] = Qs[(wrow+gid+8)*SQW + kw + tig];
            af[2] = Qs[(wrow+gid  )*SQW + kw + tig + 4];
            af[3] = Qs[(wrow+gid+8)*SQW + kw + tig + 4];
            #pragma unroll
            for (int nt = 0; nt < 8; nt++){
                uint32_t bf[2] = { Ks[(kw+tig)*SKW + nt*8 + gid],
                                   Ks[(kw+tig+4)*SKW + nt*8 + gid] };
                mma16(s[nt], af, bf);
            }
        }

        // ALiBi + causal mask + online softmax (fragment form)
        const bool diag = (kt == nkt - 1);
        const int qi0 = q0 + wrow + gid, qi1 = qi0 + 8;
        float mx0 = -1e30f, mx1 = -1e30f;
        #pragma unroll
        for (int nt = 0; nt < 8; nt++){
            #pragma unroll
            for (int e = 0; e < 2; e++){
                const int ki = k0 + nt*8 + 2*tig + e;
                float sv0 = s[nt][e]   - slope * (float)(qi0 - ki);
                float sv1 = s[nt][2+e] - slope * (float)(qi1 - ki);
                if (diag && ki > qi0) sv0 = -1e30f;
                if (diag && ki > qi1) sv1 = -1e30f;
                s[nt][e] = sv0; s[nt][2+e] = sv1;
                mx0 = fmaxf(mx0, sv0); mx1 = fmaxf(mx1, sv1);
            }
        }
        mx0 = fmaxf(mx0, __shfl_xor_sync(0xffffffffu, mx0, 1));
        mx0 = fmaxf(mx0, __shfl_xor_sync(0xffffffffu, mx0, 2));
        mx1 = fmaxf(mx1, __shfl_xor_sync(0xffffffffu, mx1, 1));
        mx1 = fmaxf(mx1, __shfl_xor_sync(0xffffffffu, mx1, 2));
        const float mn0 = fmaxf(m0, mx0), mn1 = fmaxf(m1, mx1);
        const float corr0 = __expf(m0 - mn0), corr1 = __expf(m1 - mn1);
        m0 = mn0; m1 = mn1;

        float ps0 = 0.f, ps1 = 0.f;
        #pragma unroll
        for (int nt = 0; nt < 8; nt++){
            const float p00 = __expf(s[nt][0] - mn0), p01 = __expf(s[nt][1] - mn0);
            const float p10 = __expf(s[nt][2] - mn1), p11 = __expf(s[nt][3] - mn1);
            ps0 += p00 + p01; ps1 += p10 + p11;
            Ps[(wrow+gid  )*SQW + nt*4 + tig] = pk(p00, p01);
            Ps[(wrow+gid+8)*SQW + nt*4 + tig] = pk(p10, p11);
        }
        ps0 += __shfl_xor_sync(0xffffffffu, ps0, 1);
        ps0 += __shfl_xor_sync(0xffffffffu, ps0, 2);
        ps1 += __shfl_xor_sync(0xffffffffu, ps1, 1);
        ps1 += __shfl_xor_sync(0xffffffffu, ps1, 2);
        l0 = l0 * corr0 + ps0;
        l1 = l1 * corr1 + ps1;
        #pragma unroll
        for (int nt = 0; nt < 8; nt++){
            acc[nt][0] *= corr0; acc[nt][1] *= corr0;
            acc[nt][2] *= corr1; acc[nt][3] *= corr1;
        }
        __syncwarp();   // Ps rows are warp-private; publish stores to lanes

        // acc += P @ V (4 k16 chunks over 64 keys)
        #pragma unroll
        for (int ch = 0; ch < 4; ch++){
            const int kw = ch * 8;
            uint32_t af[4];
            af[0] = Ps[(wrow+gid  )*SQW + kw + tig];
            af[1] = Ps[(wrow+gid+8)*SQW + kw + tig];
            af[2] = Ps[(wrow+gid  )*SQW + kw + tig + 4];
            af[3] = Ps[(wrow+gid+8)*SQW + kw + tig + 4];
            #pragma unroll
            for (int nt = 0; nt < 8; nt++){
                uint32_t bf[2] = { Vs[(kw+tig)*SKW + nt*8 + gid],
                                   Vs[(kw+tig+4)*SKW + nt*8 + gid] };
                mma16(acc[nt], af, bf);
            }
        }
        __syncwarp();
    }

    const float i0 = 1.f / l0, i1 = 1.f / l1;
    float* yb = Y + ((size_t)(b*T_SZ) + q0 + wrow) * C_SZ + h*HD;
    #pragma unroll
    for (int nt = 0; nt < 8; nt++){
        const int c = nt*8 + 2*tig;
        *(float2*)&yb[(size_t)gid     * C_SZ + c] = make_float2(acc[nt][0]*i0, acc[nt][1]*i0);
        *(float2*)&yb[(size_t)(gid+8) * C_SZ + c] = make_float2(acc[nt][2]*i1, acc[nt][3]*i1);
    }
}

extern "C" void kernel_launch(void* const* d_in, const int* in_sizes, int n_in,
                              void* d_out, int out_size)
{
    const float* x  = (const float*)d_in[0];
    const float* Wq = (const float*)d_in[1];
    const float* bq = (const float*)d_in[2];
    const float* Wk = (const float*)d_in[3];
    const float* bk = (const float*)d_in[4];
    const float* Wv = (const float*)d_in[5];
    const float* bv = (const float*)d_in[6];
    const float* Wo = (const float*)d_in[7];
    const float* bo = (const float*)d_in[8];
    float* out = (float*)d_out;

    float *qp, *ktp, *vp, *yp;
    cudaGetSymbolAddress((void**)&qp,  g_q);
    cudaGetSymbolAddress((void**)&ktp, g_kt);
    cudaGetSymbolAddress((void**)&vp,  g_v);
    cudaGetSymbolAddress((void**)&yp,  g_y);

    cudaFuncSetAttribute(flash_tc,
                         cudaFuncAttributeMaxDynamicSharedMemorySize, FLASH_SMEM);

    qkv_gemm<<<dim3(24, M_SZ/128), 256>>>(x, Wq, bq, Wk, bk, Wv, bv, qp, ktp, vp);

    flash_tc<<<dim3(T_SZ/64, NH, B_SZ), 128, FLASH_SMEM>>>(qp, ktp, vp, yp);

    oproj_gemm<<<dim3(C_SZ/128, M_SZ/128), 256>>>(yp, Wo, bo, out);
}

// round 7
// speedup vs baseline: 1.7671x; 1.0417x over previous
#include <cuda_runtime.h>
#include <cuda_fp16.h>
#include <math.h>
#include <stdint.h>

#define B_SZ 2
#define T_SZ 2048
#define C_SZ 1024
#define NH   16
#define HD   64
#define M_SZ (B_SZ*T_SZ)   // 4096

// Scratch (static device globals: allowed; runtime allocation is not)
__device__ __half   g_qh[B_SZ*NH*T_SZ*HD];        // [bh][t][d] half
__device__ uint32_t g_kw[B_SZ*NH*(HD/2)*T_SZ];    // [bh][d2][t] half2(d even, d odd)
__device__ __half   g_vh[B_SZ*NH*T_SZ*HD];        // [bh][t][d] half
__device__ float    g_y [M_SZ*C_SZ];              // [b*t][c] fp32

// pack two f32 -> f16x2 (lo, hi), round-to-nearest-even
__device__ __forceinline__ uint32_t pk(float lo, float hi){
    uint32_t r; asm("cvt.rn.f16x2.f32 %0, %1, %2;" : "=r"(r) : "f"(hi), "f"(lo));
    return r;
}
__device__ __forceinline__ uint32_t prmt(uint32_t a, uint32_t b, uint32_t sel){
    uint32_t r; asm("prmt.b32 %0, %1, %2, %3;" : "=r"(r) : "r"(a), "r"(b), "r"(sel));
    return r;
}

// m16n8k16 fp16 mma, fp32 accumulate, D += A*B (C aliased to D)
__device__ __forceinline__ void mma16(float* d, const uint32_t* a, const uint32_t* b){
    asm volatile("mma.sync.aligned.m16n8k16.row.col.f32.f16.f16.f32 "
        "{%0,%1,%2,%3}, {%4,%5,%6,%7}, {%8,%9}, {%0,%1,%2,%3};"
        : "+f"(d[0]), "+f"(d[1]), "+f"(d[2]), "+f"(d[3])
        : "r"(a[0]), "r"(a[1]), "r"(a[2]), "r"(a[3]), "r"(b[0]), "r"(b[1]));
}

#define MODE_PLAIN   0
#define MODE_HEADS   1
#define MODE_HEADS_T 2

// ---------------------------------------------------------------------------
// fp16 GEMM core: 128x128 tile, KC=32, 8 warps, warp tile 32x64.
// Double-buffered smem (compile-time ping-pong), one barrier per K-step.
// ---------------------------------------------------------------------------
#define KC   32
#define AS   20     // [m 128][k2 16 +4]: frag banks (20m+tig)&31 -> 32-distinct
#define BS2  136    // [k2 16][n 128 +8]: frag banks (8k2+n)&31  -> 32-distinct

__device__ __forceinline__ void gemm_core(
    const float* __restrict__ A, const float* __restrict__ W,
    const float* __restrict__ bias, void* __restrict__ outv,
    int bm, int bn, int mode)
{
    __shared__ uint32_t As[2*128*AS];
    __shared__ uint32_t Bs[2*16*BS2];

    const int tid  = threadIdx.x;
    const int warp = tid >> 5, lane = tid & 31;
    const int gid  = lane >> 2, tig = lane & 3;
    const int warpM = (warp & 3) * 32, warpN = (warp >> 2) * 64;

    const int arow = tid >> 3, acol = (tid & 7) * 4;   // A: 32 rows/pass, 4 passes
    const int k2r  = tid >> 5, bcol = (tid & 31) * 4;  // B: 8 k2-rows/pass, 2 passes

    const float* Abase = A + (size_t)(bm + arow) * C_SZ + acol;
    const float* Wb0   = W + (size_t)(2*k2r) * C_SZ + bn + bcol;

    float4 pa[4], pb0[2], pb1[2];

    auto LDG = [&](int k){
        #pragma unroll
        for (int p = 0; p < 4; p++)
            pa[p] = *(const float4*)(Abase + k + (size_t)(32*p) * C_SZ);
        #pragma unroll
        for (int p = 0; p < 2; p++){
            pb0[p] = *(const float4*)(Wb0 + (size_t)(k + 16*p) * C_SZ);
            pb1[p] = *(const float4*)(Wb0 + (size_t)(k + 16*p + 1) * C_SZ);
        }
    };
    auto STS = [&](uint32_t* Ab, uint32_t* Bb){
        #pragma unroll
        for (int p = 0; p < 4; p++)
            *(uint2*)&Ab[(arow + 32*p)*AS + (acol >> 1)] =
                make_uint2(pk(pa[p].x, pa[p].y), pk(pa[p].z, pa[p].w));
        #pragma unroll
        for (int p = 0; p < 2; p++)
            *(uint4*)&Bb[(k2r + 8*p)*BS2 + bcol] =
                make_uint4(pk(pb0[p].x, pb1[p].x), pk(pb0[p].y, pb1[p].y),
                           pk(pb0[p].z, pb1[p].z), pk(pb0[p].w, pb1[p].w));
    };

    float acc[2][8][4];
    #pragma unroll
    for (int mt = 0; mt < 2; mt++)
        #pragma unroll
        for (int nt = 0; nt < 8; nt++)
            #pragma unroll
            for (int e = 0; e < 4; e++) acc[mt][nt][e] = 0.f;

    auto COMPUTE = [&](const uint32_t* Ab, const uint32_t* Bb){
        #pragma unroll
        for (int ch = 0; ch < 2; ch++){
            const int kw = ch * 8;
            uint32_t af[2][4];
            #pragma unroll
            for (int mt = 0; mt < 2; mt++){
                const int r = warpM + mt*16 + gid;
                af[mt][0] = Ab[r*AS + kw + tig];
                af[mt][1] = Ab[(r+8)*AS + kw + tig];
                af[mt][2] = Ab[r*AS + kw + tig + 4];
                af[mt][3] = Ab[(r+8)*AS + kw + tig + 4];
            }
            #pragma unroll
            for (int nt = 0; nt < 8; nt++){
                const int c = warpN + nt*8 + gid;
                uint32_t bf[2] = { Bb[(kw+tig)*BS2 + c], Bb[(kw+tig+4)*BS2 + c] };
                mma16(acc[0][nt], af[0], bf);
                mma16(acc[1][nt], af[1], bf);
            }
        }
    };

    // Prologue: tile 0 -> buf0, tile 1 -> regs
    LDG(0);
    STS(As, Bs);
    LDG(KC);
    __syncthreads();

    for (int k0 = 0; k0 < C_SZ; k0 += 2*KC){
        // step A: compute buf0 (tile k0); regs hold k0+KC -> buf1
        {
            if (k0 + KC < C_SZ)   STS(As + 128*AS, Bs + 16*BS2);
            if (k0 + 2*KC < C_SZ) LDG(k0 + 2*KC);
            COMPUTE(As, Bs);
            __syncthreads();
        }
        // step B: compute buf1 (tile k0+KC); regs hold k0+2KC -> buf0
        if (k0 + KC < C_SZ){
            if (k0 + 2*KC < C_SZ) STS(As, Bs);
            if (k0 + 3*KC < C_SZ) LDG(k0 + 3*KC);
            COMPUTE(As + 128*AS, Bs + 16*BS2);
            __syncthreads();
        }
    }

    #pragma unroll
    for (int mt = 0; mt < 2; mt++){
        #pragma unroll
        for (int nt = 0; nt < 8; nt++){
            const int r = bm + warpM + mt*16 + gid;
            const int c = bn + warpN + nt*8 + 2*tig;
            const float b0v = bias[c], b1v = bias[c+1];
            float2 v0 = make_float2(acc[mt][nt][0] + b0v, acc[mt][nt][1] + b1v);
            float2 v1 = make_float2(acc[mt][nt][2] + b0v, acc[mt][nt][3] + b1v);
            if (mode == MODE_PLAIN){
                float* out = (float*)outv;
                *(float2*)&out[(size_t)r * C_SZ + c]     = v0;
                *(float2*)&out[(size_t)(r+8) * C_SZ + c] = v1;
            } else {
                const int b = r >> 11, t = r & 2047;
                const int h = c >> 6,  d = c & 63;
                const int bh = b*NH + h;
                if (mode == MODE_HEADS){
                    __half* out = (__half*)outv;
                    *(uint32_t*)&out[((size_t)bh * T_SZ + t    ) * HD + d] = pk(v0.x, v0.y);
                    *(uint32_t*)&out[((size_t)bh * T_SZ + t + 8) * HD + d] = pk(v1.x, v1.y);
                } else {
                    uint32_t* out = (uint32_t*)outv;
                    const size_t base = ((size_t)bh * (HD/2) + (d >> 1)) * T_SZ + t;
                    out[base]     = pk(v0.x, v0.y);
                    out[base + 8] = pk(v1.x, v1.y);
                }
            }
        }
    }
}

// Fused QKV: grid.x = 24 (8 n-blocks x 3 matrices), grid.y = 32 (m-blocks)
__global__ __launch_bounds__(256, 2)
void qkv_gemm(const float* __restrict__ x,
              const float* __restrict__ Wq, const float* __restrict__ bq,
              const float* __restrict__ Wk, const float* __restrict__ bk,
              const float* __restrict__ Wv, const float* __restrict__ bv,
              __half* __restrict__ q, uint32_t* __restrict__ kt, __half* __restrict__ v)
{
    const int bx = blockIdx.x;
    const int which = bx >> 3;
    const int bn = (bx & 7) * 128;
    const int bm = blockIdx.y * 128;
    const float* W    = (which == 0) ? Wq : (which == 1) ? Wk : Wv;
    const float* bias = (which == 0) ? bq : (which == 1) ? bk : bv;
    void* out         = (which == 0) ? (void*)q : (which == 1) ? (void*)kt : (void*)v;
    const int mode    = (which == 1) ? MODE_HEADS_T : MODE_HEADS;
    gemm_core(x, W, bias, out, bm, bn, mode);
}

__global__ __launch_bounds__(256, 2)
void oproj_gemm(const float* __restrict__ A, const float* __restrict__ W,
                const float* __restrict__ bias, float* __restrict__ out)
{
    gemm_core(A, W, bias, out, blockIdx.y * 128, blockIdx.x * 128, MODE_PLAIN);
}

// ---------------------------------------------------------------------------
// Flash attention, fp16 mma. 128 thr (4 warps), BQ=64 (16 rows/warp), BK=64.
// Q/K/V scratch already fp16 in mma-friendly layouts: smem fills are raw
// copies (K,Q) or a 2-PRMT t-pair merge (V). Softmax folds the 1/8 scale.
// ---------------------------------------------------------------------------
#define SQW 36   // Qs/Ps rows: [q][32 words +4]
#define SKW 72   // Ks [d2][64+8], Vs [t2][64+8]: frag banks (8row+n) 32-distinct
#define FLASH_SMEM ((64*SQW + 32*SKW + 32*SKW + 64*SQW) * 4)

__global__ __launch_bounds__(128, 4)
void flash_tc(const __half* __restrict__ Q, const uint32_t* __restrict__ Kw,
              const __half* __restrict__ V, float* __restrict__ Y)
{
    extern __shared__ uint32_t smbuf[];
    uint32_t* Qs = smbuf;            // [64 q][SQW]   A-operand
    uint32_t* Ks = Qs + 64*SQW;      // [32 d2][SKW]  B-operand (S)
    uint32_t* Vs = Ks + 32*SKW;      // [32 t2][SKW]  B-operand (PV)
    uint32_t* Ps = Vs + 32*SKW;      // [64 q][SQW]   A-operand

    const int tid  = threadIdx.x;
    const int warp = tid >> 5, lane = tid & 31;
    const int gid  = lane >> 2, tig = lane & 3;
    const int qt   = (int)gridDim.x - 1 - (int)blockIdx.x;  // heavy blocks first
    const int h    = blockIdx.y, b = blockIdx.z;
    const int bh   = b * NH + h;
    const int q0   = qt * 64;
    const int wrow = warp * 16;
    const float slope = exp2f(-0.5f * (float)(h + 1));

    {   // Q tile: raw copy, 64 rows x 32 words
        const uint32_t* qb = (const uint32_t*)(Q + ((size_t)bh * T_SZ + q0) * HD);
        const int qr = tid >> 3, qc = (tid & 7) * 4;
        #pragma unroll
        for (int p = 0; p < 4; p++)
            *(uint4*)&Qs[(qr + 16*p)*SQW + qc] = *(const uint4*)&qb[(qr + 16*p)*32 + qc];
    }

    const uint32_t* kb_base = Kw + (size_t)bh * (HD/2) * T_SZ;    // [d2][t] words
    const __half*   vb_base = V  + (size_t)bh * T_SZ * HD;        // [t][d] half

    const int kr = tid >> 4, kc = (tid & 15) * 4;   // K loader: 8 rows/pass x 4
    const int vt2 = tid >> 2, vseg = tid & 3;       // V loader: t2, 16-half segment

    float m0 = -1e30f, m1 = -1e30f, l0 = 0.f, l1 = 0.f;
    float acc[8][4] = {};

    const int nkt = qt + 1;
    for (int kt = 0; kt < nkt; kt++){
        const int k0 = kt * 64;
        __syncthreads();   // previous tile's matmuls done with Ks/Vs
        {   // K tile: raw word copy, 32 rows(d2) x 64 words(keys)
            #pragma unroll
            for (int p = 0; p < 4; p++)
                *(uint4*)&Ks[(kr + 8*p)*SKW + kc] =
                    *(const uint4*)&kb_base[(size_t)(kr + 8*p) * T_SZ + k0 + kc];
            // V tile: merge adjacent-t rows into half2 pairs via PRMT
            const __half* v0p = vb_base + (size_t)(k0 + 2*vt2) * HD + vseg*16;
            uint4 e0 = *(const uint4*)(v0p);
            uint4 e1 = *(const uint4*)(v0p + 8);
            uint4 o0 = *(const uint4*)(v0p + HD);
            uint4 o1 = *(const uint4*)(v0p + HD + 8);
            uint32_t* vd = &Vs[vt2*SKW + vseg*16];
            *(uint4*)(vd    ) = make_uint4(prmt(e0.x,o0.x,0x5410), prmt(e0.x,o0.x,0x7632),
                                           prmt(e0.y,o0.y,0x5410), prmt(e0.y,o0.y,0x7632));
            *(uint4*)(vd + 4) = make_uint4(prmt(e0.z,o0.z,0x5410), prmt(e0.z,o0.z,0x7632),
                                           prmt(e0.w,o0.w,0x5410), prmt(e0.w,o0.w,0x7632));
            *(uint4*)(vd + 8) = make_uint4(prmt(e1.x,o1.x,0x5410), prmt(e1.x,o1.x,0x7632),
                                           prmt(e1.y,o1.y,0x5410), prmt(e1.y,o1.y,0x7632));
            *(uint4*)(vd +12) = make_uint4(prmt(e1.z,o1.z,0x5410), prmt(e1.z,o1.z,0x7632),
                                           prmt(e1.w,o1.w,0x5410), prmt(e1.w,o1.w,0x7632));
        }
        __syncthreads();   // publish K/V (and Qs on iter 0)

        // S = Q K^T : warp computes its 16 rows x 64 keys (4 k16 chunks)
        float s[8][4] = {};
        #pragma unroll
        for (int ch = 0; ch < 4; ch++){
            const int kw = ch * 8;
            uint32_t af[4];
            af[0] = Qs[(wrow+gid  )*SQW + kw + tig];
            af[1] = Qs[(wrow+gid+8)*SQW + kw + tig];
            af[2] = Qs[(wrow+gid  )*SQW + kw + tig + 4];
            af[3] = Qs[(wrow+gid+8)*SQW + kw + tig + 4];
            #pragma unroll
            for (int nt = 0; nt < 8; nt++){
                uint32_t bf[2] = { Ks[(kw+tig)*SKW + nt*8 + gid],
                                   Ks[(kw+tig+4)*SKW + nt*8 + gid] };
                mma16(s[nt], af, bf);
            }
        }

        // scale (1/8) + ALiBi + causal mask + online softmax
        const bool diag = (kt == nkt - 1);
        const int qi0 = q0 + wrow + gid, qi1 = qi0 + 8;
        float mx0 = -1e30f, mx1 = -1e30f;
        #pragma unroll
        for (int nt = 0; nt < 8; nt++){
            #pragma unroll
            for (int e = 0; e < 2; e++){
                const int ki = k0 + nt*8 + 2*tig + e;
                float sv0 = fmaf(s[nt][e],   0.125f, slope * (float)(ki - qi0));
                float sv1 = fmaf(s[nt][2+e], 0.125f, slope * (float)(ki - qi1));
                if (diag && ki > qi0) sv0 = -1e30f;
                if (diag && ki > qi1) sv1 = -1e30f;
                s[nt][e] = sv0; s[nt][2+e] = sv1;
                mx0 = fmaxf(mx0, sv0); mx1 = fmaxf(mx1, sv1);
            }
        }
        mx0 = fmaxf(mx0, __shfl_xor_sync(0xffffffffu, mx0, 1));
        mx0 = fmaxf(mx0, __shfl_xor_sync(0xffffffffu, mx0, 2));
        mx1 = fmaxf(mx1, __shfl_xor_sync(0xffffffffu, mx1, 1));
        mx1 = fmaxf(mx1, __shfl_xor_sync(0xffffffffu, mx1, 2));
        const float mn0 = fmaxf(m0, mx0), mn1 = fmaxf(m1, mx1);
        const float corr0 = __expf(m0 - mn0), corr1 = __expf(m1 - mn1);
        m0 = mn0; m1 = mn1;

        float ps0 = 0.f, ps1 = 0.f;
        #pragma unroll
        for (int nt = 0; nt < 8; nt++){
            const float p00 = __expf(s[nt][0] - mn0), p01 = __expf(s[nt][1] - mn0);
            const float p10 = __expf(s[nt][2] - mn1), p11 = __expf(s[nt][3] - mn1);
            ps0 += p00 + p01; ps1 += p10 + p11;
            Ps[(wrow+gid  )*SQW + nt*4 + tig] = pk(p00, p01);
            Ps[(wrow+gid+8)*SQW + nt*4 + tig] = pk(p10, p11);
        }
        ps0 += __shfl_xor_sync(0xffffffffu, ps0, 1);
        ps0 += __shfl_xor_sync(0xffffffffu, ps0, 2);
        ps1 += __shfl_xor_sync(0xffffffffu, ps1, 1);
        ps1 += __shfl_xor_sync(0xffffffffu, ps1, 2);
        l0 = l0 * corr0 + ps0;
        l1 = l1 * corr1 + ps1;
        #pragma unroll
        for (int nt = 0; nt < 8; nt++){
            acc[nt][0] *= corr0; acc[nt][1] *= corr0;
            acc[nt][2] *= corr1; acc[nt][3] *= corr1;
        }
        __syncwarp();   // Ps rows are warp-private; publish stores to lanes

        // acc += P @ V (4 k16 chunks over 64 keys)
        #pragma unroll
        for (int ch = 0; ch < 4; ch++){
            const int kw = ch * 8;
            uint32_t af[4];
            af[0] = Ps[(wrow+gid  )*SQW + kw + tig];
            af[1] = Ps[(wrow+gid+8)*SQW + kw + tig];
            af[2] = Ps[(wrow+gid  )*SQW + kw + tig + 4];
            af[3] = Ps[(wrow+gid+8)*SQW + kw + tig + 4];
            #pragma unroll
            for (int nt = 0; nt < 8; nt++){
                uint32_t bf[2] = { Vs[(kw+tig)*SKW + nt*8 + gid],
                                   Vs[(kw+tig+4)*SKW + nt*8 + gid] };
                mma16(acc[nt], af, bf);
            }
        }
        __syncwarp();
    }

    const float i0 = 1.f / l0, i1 = 1.f / l1;
    float* yb = Y + ((size_t)(b*T_SZ) + q0 + wrow) * C_SZ + h*HD;
    #pragma unroll
    for (int nt = 0; nt < 8; nt++){
        const int c = nt*8 + 2*tig;
        *(float2*)&yb[(size_t)gid     * C_SZ + c] = make_float2(acc[nt][0]*i0, acc[nt][1]*i0);
        *(float2*)&yb[(size_t)(gid+8) * C_SZ + c] = make_float2(acc[nt][2]*i1, acc[nt][3]*i1);
    }
}

extern "C" void kernel_launch(void* const* d_in, const int* in_sizes, int n_in,
                              void* d_out, int out_size)
{
    const float* x  = (const float*)d_in[0];
    const float* Wq = (const float*)d_in[1];
    const float* bq = (const float*)d_in[2];
    const float* Wk = (const float*)d_in[3];
    const float* bk = (const float*)d_in[4];
    const float* Wv = (const float*)d_in[5];
    const float* bv = (const float*)d_in[6];
    const float* Wo = (const float*)d_in[7];
    const float* bo = (const float*)d_in[8];
    float* out = (float*)d_out;

    __half *qp, *vp; uint32_t *ktp; float *yp;
    cudaGetSymbolAddress((void**)&qp,  g_qh);
    cudaGetSymbolAddress((void**)&ktp, g_kw);
    cudaGetSymbolAddress((void**)&vp,  g_vh);
    cudaGetSymbolAddress((void**)&yp,  g_y);

    cudaFuncSetAttribute(flash_tc,
                         cudaFuncAttributeMaxDynamicSharedMemorySize, FLASH_SMEM);

    qkv_gemm<<<dim3(24, M_SZ/128), 256>>>(x, Wq, bq, Wk, bk, Wv, bv, qp, ktp, vp);

    flash_tc<<<dim3(T_SZ/64, NH, B_SZ), 128, FLASH_SMEM>>>(qp, ktp, vp, yp);

    oproj_gemm<<<dim3(C_SZ/128, M_SZ/128), 256>>>(yp, Wo, bo, out);
}

// round 9
// speedup vs baseline: 1.9233x; 1.0884x over previous
#include <cuda_runtime.h>
#include <cuda_fp16.h>
#include <math.h>
#include <stdint.h>

#define B_SZ 2
#define T_SZ 2048
#define C_SZ 1024
#define NH   16
#define HD   64
#define M_SZ (B_SZ*T_SZ)   // 4096

// Scratch (static device globals: allowed; runtime allocation is not)
__device__ __align__(256) __half   g_xh[M_SZ*C_SZ];           // x as fp16 [m][k]
__device__ __align__(256) uint32_t g_wt[4*C_SZ*(C_SZ/2)];     // W^T fp16 [w][n][k2] words
__device__ __align__(256) __half   g_qh[B_SZ*NH*T_SZ*HD];     // [bh][t][d]
__device__ __align__(256) uint32_t g_kw[B_SZ*NH*(HD/2)*T_SZ]; // [bh][d2][t] half2(d,d+1)
__device__ __align__(256) __half   g_vh[B_SZ*NH*T_SZ*HD];     // [bh][t][d]
__device__ __align__(256) __half   g_yh[M_SZ*C_SZ];           // attention out fp16 [m][c]

// ---------------------------------------------------------------------------
// helpers
// ---------------------------------------------------------------------------
__device__ __forceinline__ uint32_t pk(float lo, float hi){
    uint32_t r; asm("cvt.rn.f16x2.f32 %0, %1, %2;" : "=r"(r) : "f"(hi), "f"(lo));
    return r;
}
__device__ __forceinline__ uint32_t prmt(uint32_t a, uint32_t b, uint32_t sel){
    uint32_t r; asm("prmt.b32 %0, %1, %2, %3;" : "=r"(r) : "r"(a), "r"(b), "r"(sel));
    return r;
}
__device__ __forceinline__ uint32_t smem_u32(const void* p){
    uint32_t a;
    asm("{ .reg .u64 t; cvta.to.shared.u64 t, %1; cvt.u32.u64 %0, t; }"
        : "=r"(a) : "l"(p));
    return a;
}

// m16n8k16 fp16 mma, fp32 accumulate, D += A*B (C aliased to D)
__device__ __forceinline__ void mma16(float* d, const uint32_t* a, const uint32_t* b){
    asm volatile("mma.sync.aligned.m16n8k16.row.col.f32.f16.f16.f32 "
        "{%0,%1,%2,%3}, {%4,%5,%6,%7}, {%8,%9}, {%0,%1,%2,%3};"
        : "+f"(d[0]), "+f"(d[1]), "+f"(d[2]), "+f"(d[3])
        : "r"(a[0]), "r"(a[1]), "r"(a[2]), "r"(a[3]), "r"(b[0]), "r"(b[1]));
}

// ldmatrix x4: four 8x8 b16 matrices; lane l supplies row address for
// matrix group g = l>>3, row r = l&7. Result reg j = matrix of group j,
// thread (gid,tig) holds (row gid, halves 2tig, 2tig+1) of each matrix.
__device__ __forceinline__ void ldsm4(uint32_t* r, uint32_t saddr){
    asm volatile("ldmatrix.sync.aligned.m8n8.x4.shared.b16 {%0,%1,%2,%3}, [%4];"
        : "=r"(r[0]), "=r"(r[1]), "=r"(r[2]), "=r"(r[3]) : "r"(saddr));
}

// ---------------------------------------------------------------------------
// prep kernels: x -> fp16 [m][k]; W[k][n] fp32 -> W^T [n][k] fp16 words
// ---------------------------------------------------------------------------
__global__ void prep_x(const float* __restrict__ x, uint32_t* __restrict__ xh){
    const int i = blockIdx.x * blockDim.x + threadIdx.x;
    #pragma unroll
    for (int p = 0; p < 4; p++){
        float2 v = ((const float2*)x)[i + p*524288];
        xh[i + p*524288] = pk(v.x, v.y);
    }
}

__global__ void prep_w(const float* __restrict__ Wq, const float* __restrict__ Wk,
                       const float* __restrict__ Wv, const float* __restrict__ Wo,
                       uint32_t* __restrict__ Wt){
    __shared__ float s[64][65];
    const int wsel = blockIdx.z;
    const float* W = (wsel==0)?Wq:(wsel==1)?Wk:(wsel==2)?Wv:Wo;
    const int k0 = blockIdx.y*64, n0 = blockIdx.x*64;
    const int tid = threadIdx.x;
    #pragma unroll
    for (int p = 0; p < 16; p++){
        const int lin = tid + p*256, kk = lin >> 6, nn = lin & 63;
        s[kk][nn] = W[(size_t)(k0+kk)*C_SZ + n0 + nn];
    }
    __syncthreads();
    uint32_t* out = Wt + (size_t)wsel * C_SZ * (C_SZ/2);
    #pragma unroll
    for (int p = 0; p < 8; p++){
        const int lin = tid + p*256, nn = lin >> 5, k2 = lin & 31;
        out[(size_t)(n0+nn)*(C_SZ/2) + (k0 >> 1) + k2] = pk(s[2*k2][nn], s[2*k2+1][nn]);
    }
}

// ---------------------------------------------------------------------------
// fp16 ldmatrix GEMM: 128x128 block tile, KC=64 halves, 8 warps (4m x 2n),
// warp tile 32m x 64n. Both smem tiles [row][64 halves] = 128B rows with
// Swizzle<3,3,3> (16B chunk c -> c ^ (row&7)): LDSM wavefronts hit all 32
// banks; STS 8-lane groups hit all 32 banks; LDG is 128B-contiguous per
// 8 lanes. MODE 0 = fused QKV -> fp16 scratch; MODE 1 = O-proj -> fp32.
// ---------------------------------------------------------------------------
#define MODE_PLAIN   0
#define MODE_HEADS   1
#define MODE_HEADS_T 2
#define KC 64

template<int MODE>
__global__ __launch_bounds__(256, 2)
void lm_gemm(const __half* __restrict__ Aall, const uint32_t* __restrict__ Wt,
             const float* __restrict__ b0, const float* __restrict__ b1,
             const float* __restrict__ b2,
             void* __restrict__ o0, void* __restrict__ o1, void* __restrict__ o2)
{
    __shared__ uint4 Asm[128*8];   // [row m][8 chunks of 16B]
    __shared__ uint4 Bsm[128*8];   // [row n][8 chunks of 16B]

    const int tid  = threadIdx.x;
    const int warp = tid >> 5, lane = tid & 31;
    const int gid  = lane >> 2, tig = lane & 3;
    const int warpM = (warp & 3) * 32, warpN = (warp >> 2) * 64;

    int which, bn, bm; const float* bias; void* outv;
    if (MODE == 0){
        which = blockIdx.x >> 3;
        bn = (blockIdx.x & 7) * 128;
        bm = blockIdx.y * 128;
        bias = (which==0)?b0:(which==1)?b1:b2;
        outv = (which==0)?o0:(which==1)?o1:o2;
    } else {
        which = 3; bn = blockIdx.x * 128; bm = blockIdx.y * 128;
        bias = b0; outv = o0;
    }
    const int mode = (MODE == 1) ? MODE_PLAIN : ((which == 1) ? MODE_HEADS_T : MODE_HEADS);

    const uint32_t As_u = smem_u32(Asm), Bs_u = smem_u32(Bsm);

    // ldmatrix lane-constant coords
    const int a_m  = lane & 15, a_kg = lane >> 4;          // A: rows m0-15, k-group
    const int b_n  = (lane & 7) + ((lane >> 4) << 3);      // B: n within 16-col pair
    const int b_kg = (lane >> 3) & 1;

    // loader coords: 4 passes, each thread one uint4 per tile per pass
    const int lrow = tid >> 3, lseg = tid & 7;             // rows 0-31 (+32p), seg 0-7

    const __half*   Ah = Aall + (size_t)bm * C_SZ;
    const uint32_t* Bw = Wt + ((size_t)which * C_SZ + bn) * (C_SZ/2);

    uint4 pa[4], pb[4];
    auto LDG = [&](int k0){
        #pragma unroll
        for (int p = 0; p < 4; p++){
            const int row = lrow + 32*p;
            pa[p] = *(const uint4*)(Ah + (size_t)row*C_SZ + k0 + lseg*8);
            pb[p] = *(const uint4*)(Bw + (size_t)row*(C_SZ/2) + (k0>>1) + lseg*4);
        }
    };
    auto STS = [&](){
        #pragma unroll
        for (int p = 0; p < 4; p++){
            const int row = lrow + 32*p;
            const int sc  = lseg ^ (row & 7);
            Asm[row*8 + sc] = pa[p];
            Bsm[row*8 + sc] = pb[p];
        }
    };

    float acc[2][8][4];
    #pragma unroll
    for (int mt = 0; mt < 2; mt++)
        #pragma unroll
        for (int nt = 0; nt < 8; nt++)
            #pragma unroll
            for (int e = 0; e < 4; e++) acc[mt][nt][e] = 0.f;

    LDG(0);
    for (int i = 0; i < C_SZ/KC; i++){
        STS();
        __syncthreads();
        if (i + 1 < C_SZ/KC) LDG((i+1)*KC);

        #pragma unroll
        for (int kw = 0; kw < KC; kw += 16){
            const int cb = kw >> 3;
            uint32_t a[2][4];
            #pragma unroll
            for (int mt = 0; mt < 2; mt++){
                const int row = warpM + mt*16 + a_m;
                ldsm4(a[mt], As_u + row*128 + (((cb + a_kg) ^ (row & 7)) << 4));
            }
            #pragma unroll
            for (int j = 0; j < 4; j++){
                uint32_t bf[4];
                const int row = warpN + j*16 + b_n;
                ldsm4(bf, Bs_u + row*128 + (((cb + b_kg) ^ (row & 7)) << 4));
                mma16(acc[0][2*j  ], a[0], bf);
                mma16(acc[0][2*j+1], a[0], bf + 2);
                mma16(acc[1][2*j  ], a[1], bf);
                mma16(acc[1][2*j+1], a[1], bf + 2);
            }
        }
        __syncthreads();
    }

    #pragma unroll
    for (int mt = 0; mt < 2; mt++){
        #pragma unroll
        for (int nt = 0; nt < 8; nt++){
            const int r = bm + warpM + mt*16 + gid;
            const int c = bn + warpN + nt*8 + 2*tig;
            const float b0v = bias[c], b1v = bias[c+1];
            float2 v0 = make_float2(acc[mt][nt][0] + b0v, acc[mt][nt][1] + b1v);
            float2 v1 = make_float2(acc[mt][nt][2] + b0v, acc[mt][nt][3] + b1v);
            if (mode == MODE_PLAIN){
                float* out = (float*)outv;
                *(float2*)&out[(size_t)r * C_SZ + c]     = v0;
                *(float2*)&out[(size_t)(r+8) * C_SZ + c] = v1;
            } else {
                const int b = r >> 11, t = r & 2047;
                const int h = c >> 6,  d = c & 63;
                const int bh = b*NH + h;
                if (mode == MODE_HEADS){
                    __half* out = (__half*)outv;
                    *(uint32_t*)&out[((size_t)bh * T_SZ + t    ) * HD + d] = pk(v0.x, v0.y);
                    *(uint32_t*)&out[((size_t)bh * T_SZ + t + 8) * HD + d] = pk(v1.x, v1.y);
                } else {
                    uint32_t* out = (uint32_t*)outv;
                    const size_t base = ((size_t)bh * (HD/2) + (d >> 1)) * T_SZ + t;
                    out[base]     = pk(v0.x, v0.y);
                    out[base + 8] = pk(v1.x, v1.y);
                }
            }
        }
    }
}

// ---------------------------------------------------------------------------
// Flash attention (R6-proven body, fp16 output). 128 thr, BQ=64, BK=64.
// ---------------------------------------------------------------------------
#define SQW 36
#define SKW 72
#define FLASH_SMEM ((64*SQW + 32*SKW + 32*SKW + 64*SQW) * 4)

__global__ __launch_bounds__(128, 4)
void flash_tc(const __half* __restrict__ Q, const uint32_t* __restrict__ Kw,
              const __half* __restrict__ V, uint32_t* __restrict__ Yw)
{
    extern __shared__ uint32_t smbuf[];
    uint32_t* Qs = smbuf;
    uint32_t* Ks = Qs + 64*SQW;
    uint32_t* Vs = Ks + 32*SKW;
    uint32_t* Ps = Vs + 32*SKW;

    const int tid  = threadIdx.x;
    const int warp = tid >> 5, lane = tid & 31;
    const int gid  = lane >> 2, tig = lane & 3;
    const int qt   = (int)gridDim.x - 1 - (int)blockIdx.x;
    const int h    = blockIdx.y, b = blockIdx.z;
    const int bh   = b * NH + h;
    const int q0   = qt * 64;
    const int wrow = warp * 16;
    const float slope = exp2f(-0.5f * (float)(h + 1));

    {
        const uint32_t* qb = (const uint32_t*)(Q + ((size_t)bh * T_SZ + q0) * HD);
        const int qr = tid >> 3, qc = (tid & 7) * 4;
        #pragma unroll
        for (int p = 0; p < 4; p++)
            *(uint4*)&Qs[(qr + 16*p)*SQW + qc] = *(const uint4*)&qb[(qr + 16*p)*32 + qc];
    }

    const uint32_t* kb_base = Kw + (size_t)bh * (HD/2) * T_SZ;
    const __half*   vb_base = V  + (size_t)bh * T_SZ * HD;

    const int kr = tid >> 4, kc = (tid & 15) * 4;
    const int vt2 = tid >> 2, vseg = tid & 3;

    float m0 = -1e30f, m1 = -1e30f, l0 = 0.f, l1 = 0.f;
    float acc[8][4] = {};

    const int nkt = qt + 1;
    for (int kt = 0; kt < nkt; kt++){
        const int k0 = kt * 64;
        __syncthreads();
        {
            #pragma unroll
            for (int p = 0; p < 4; p++)
                *(uint4*)&Ks[(kr + 8*p)*SKW + kc] =
                    *(const uint4*)&kb_base[(size_t)(kr + 8*p) * T_SZ + k0 + kc];
            const __half* v0p = vb_base + (size_t)(k0 + 2*vt2) * HD + vseg*16;
            uint4 e0 = *(const uint4*)(v0p);
            uint4 e1 = *(const uint4*)(v0p + 8);
            uint4 o0 = *(const uint4*)(v0p + HD);
            uint4 o1 = *(const uint4*)(v0p + HD + 8);
            uint32_t* vd = &Vs[vt2*SKW + vseg*16];
            *(uint4*)(vd    ) = make_uint4(prmt(e0.x,o0.x,0x5410), prmt(e0.x,o0.x,0x7632),
                                           prmt(e0.y,o0.y,0x5410), prmt(e0.y,o0.y,0x7632));
            *(uint4*)(vd + 4) = make_uint4(prmt(e0.z,o0.z,0x5410), prmt(e0.z,o0.z,0x7632),
                                           prmt(e0.w,o0.w,0x5410), prmt(e0.w,o0.w,0x7632));
            *(uint4*)(vd + 8) = make_uint4(prmt(e1.x,o1.x,0x5410), prmt(e1.x,o1.x,0x7632),
                                           prmt(e1.y,o1.y,0x5410), prmt(e1.y,o1.y,0x7632));
            *(uint4*)(vd +12) = make_uint4(prmt(e1.z,o1.z,0x5410), prmt(e1.z,o1.z,0x7632),
                                           prmt(e1.w,o1.w,0x5410), prmt(e1.w,o1.w,0x7632));
        }
        __syncthreads();

        float s[8][4] = {};
        #pragma unroll
        for (int ch = 0; ch < 4; ch++){
            const int kw = ch * 8;
            uint32_t af[4];
            af[0] = Qs[(wrow+gid  )*SQW + kw + tig];
            af[1] = Qs[(wrow+gid+8)*SQW + kw + tig];
            af[2] = Qs[(wrow+gid  )*SQW + kw + tig + 4];
            af[3] = Qs[(wrow+gid+8)*SQW + kw + tig + 4];
            #pragma unroll
            for (int nt = 0; nt < 8; nt++){
                uint32_t bf[2] = { Ks[(kw+tig)*SKW + nt*8 + gid],
                                   Ks[(kw+tig+4)*SKW + nt*8 + gid] };
                mma16(s[nt], af, bf);
            }
        }

        const bool diag = (kt == nkt - 1);
        const int qi0 = q0 + wrow + gid, qi1 = qi0 + 8;
        float mx0 = -1e30f, mx1 = -1e30f;
        #pragma unroll
        for (int nt = 0; nt < 8; nt++){
            #pragma unroll
            for (int e = 0; e < 2; e++){
                const int ki = k0 + nt*8 + 2*tig + e;
                float sv0 = fmaf(s[nt][e],   0.125f, slope * (float)(ki - qi0));
                float sv1 = fmaf(s[nt][2+e], 0.125f, slope * (float)(ki - qi1));
                if (diag && ki > qi0) sv0 = -1e30f;
                if (diag && ki > qi1) sv1 = -1e30f;
                s[nt][e] = sv0; s[nt][2+e] = sv1;
                mx0 = fmaxf(mx0, sv0); mx1 = fmaxf(mx1, sv1);
            }
        }
        mx0 = fmaxf(mx0, __shfl_xor_sync(0xffffffffu, mx0, 1));
        mx0 = fmaxf(mx0, __shfl_xor_sync(0xffffffffu, mx0, 2));
        mx1 = fmaxf(mx1, __shfl_xor_sync(0xffffffffu, mx1, 1));
        mx1 = fmaxf(mx1, __shfl_xor_sync(0xffffffffu, mx1, 2));
        const float mn0 = fmaxf(m0, mx0), mn1 = fmaxf(m1, mx1);
        const float corr0 = __expf(m0 - mn0), corr1 = __expf(m1 - mn1);
        m0 = mn0; m1 = mn1;

        float ps0 = 0.f, ps1 = 0.f;
        #pragma unroll
        for (int nt = 0; nt < 8; nt++){
            const float p00 = __expf(s[nt][0] - mn0), p01 = __expf(s[nt][1] - mn0);
            const float p10 = __expf(s[nt][2] - mn1), p11 = __expf(s[nt][3] - mn1);
            ps0 += p00 + p01; ps1 += p10 + p11;
            Ps[(wrow+gid  )*SQW + nt*4 + tig] = pk(p00, p01);
            Ps[(wrow+gid+8)*SQW + nt*4 + tig] = pk(p10, p11);
        }
        ps0 += __shfl_xor_sync(0xffffffffu, ps0, 1);
        ps0 += __shfl_xor_sync(0xffffffffu, ps0, 2);
        ps1 += __shfl_xor_sync(0xffffffffu, ps1, 1);
        ps1 += __shfl_xor_sync(0xffffffffu, ps1, 2);
        l0 = l0 * corr0 + ps0;
        l1 = l1 * corr1 + ps1;
        #pragma unroll
        for (int nt = 0; nt < 8; nt++){
            acc[nt][0] *= corr0; acc[nt][1] *= corr0;
            acc[nt][2] *= corr1; acc[nt][3] *= corr1;
        }
        __syncwarp();

        #pragma unroll
        for (int ch = 0; ch < 4; ch++){
            const int kw = ch * 8;
            uint32_t af[4];
            af[0] = Ps[(wrow+gid  )*SQW + kw + tig];
            af[1] = Ps[(wrow+gid+8)*SQW + kw + tig];
            af[2] = Ps[(wrow+gid  )*SQW + kw + tig + 4];
            af[3] = Ps[(wrow+gid+8)*SQW + kw + tig + 4];
            #pragma unroll
            for (int nt = 0; nt < 8; nt++){
                uint32_t bf[2] = { Vs[(kw+tig)*SKW + nt*8 + gid],
                                   Vs[(kw+tig+4)*SKW + nt*8 + gid] };
                mma16(acc[nt], af, bf);
            }
        }
        __syncwarp();
    }

    const float i0 = 1.f / l0, i1 = 1.f / l1;
    const size_t mrow = (size_t)(b*T_SZ) + q0 + wrow;
    #pragma unroll
    for (int nt = 0; nt < 8; nt++){
        const int c = nt*8 + 2*tig;
        const int wc = (h*HD + c) >> 1;
        Yw[(mrow + gid    )*(C_SZ/2) + wc] = pk(acc[nt][0]*i0, acc[nt][1]*i0);
        Yw[(mrow + gid + 8)*(C_SZ/2) + wc] = pk(acc[nt][2]*i1, acc[nt][3]*i1);
    }
}

extern "C" void kernel_launch(void* const* d_in, const int* in_sizes, int n_in,
                              void* d_out, int out_size)
{
    const float* x  = (const float*)d_in[0];
    const float* Wq = (const float*)d_in[1];
    const float* bq = (const float*)d_in[2];
    const float* Wk = (const float*)d_in[3];
    const float* bk = (const float*)d_in[4];
    const float* Wv = (const float*)d_in[5];
    const float* bv = (const float*)d_in[6];
    const float* Wo = (const float*)d_in[7];
    const float* bo = (const float*)d_in[8];
    float* out = (float*)d_out;

    __half *xhp, *qp, *vp, *yhp; uint32_t *wtp, *ktp;
    cudaGetSymbolAddress((void**)&xhp, g_xh);
    cudaGetSymbolAddress((void**)&wtp, g_wt);
    cudaGetSymbolAddress((void**)&qp,  g_qh);
    cudaGetSymbolAddress((void**)&ktp, g_kw);
    cudaGetSymbolAddress((void**)&vp,  g_vh);
    cudaGetSymbolAddress((void**)&yhp, g_yh);

    cudaFuncSetAttribute(flash_tc, cudaFuncAttributeMaxDynamicSharedMemorySize, FLASH_SMEM);

    prep_x<<<2048, 256>>>(x, (uint32_t*)xhp);
    prep_w<<<dim3(16, 16, 4), 256>>>(Wq, Wk, Wv, Wo, wtp);

    lm_gemm<0><<<dim3(24, 32), 256>>>(xhp, wtp, bq, bk, bv,
                                      (void*)qp, (void*)ktp, (void*)vp);

    flash_tc<<<dim3(T_SZ/64, NH, B_SZ), 128, FLASH_SMEM>>>(qp, ktp, vp, (uint32_t*)yhp);

    lm_gemm<1><<<dim3(8, 32), 256>>>(yhp, wtp, bo, nullptr, nullptr,
                                     (void*)out, nullptr, nullptr);
}